// round 3
// baseline (speedup 1.0000x reference)
#include <cuda_runtime.h>
#include <math.h>

#define SEQ   4096
#define DM    1024
#define DI    2048
#define NST   16
#define NL    4
#define NCH   64     // number of scan chunks
#define CHUNK 64     // steps per chunk  (NCH*CHUNK == SEQ)
#define KSPLIT 8

// ---------------- scratch (device globals; no allocation allowed) ----------
__device__ float g_enc[SEQ*DM];
__device__ float g_hbuf[SEQ*DM];
__device__ float g_xz[SEQ*2*DI];
__device__ float g_u[SEQ*DI];
__device__ float g_dbcp[KSPLIT*SEQ*96];
__device__ float g_dbc[SEQ*96];
__device__ float g_delta[SEQ*DI];
__device__ float g_y[SEQ*DI];
__device__ float g_y2[SEQ*DI];
__device__ float g_hl[NCH*NST*DI];
__device__ float g_pp[NCH*NST*DI];
__device__ float g_h0[NCH*NST*DI];

// ---------------- block reduce (sum, sumsq) --------------------------------
__device__ __forceinline__ float2 block_reduce2(float sx, float sq) {
    __shared__ float shx[8], shq[8];
    const unsigned m = 0xffffffffu;
    #pragma unroll
    for (int o = 16; o > 0; o >>= 1) {
        sx += __shfl_xor_sync(m, sx, o);
        sq += __shfl_xor_sync(m, sq, o);
    }
    int w = threadIdx.x >> 5;
    if ((threadIdx.x & 31) == 0) { shx[w] = sx; shq[w] = sq; }
    __syncthreads();
    if (threadIdx.x == 0) {
        float ax = 0.f, aq = 0.f;
        #pragma unroll
        for (int i = 0; i < 8; i++) { ax += shx[i]; aq += shq[i]; }
        shx[0] = ax; shq[0] = aq;
    }
    __syncthreads();
    return make_float2(shx[0], shq[0]);
}

// ---------------- layernorm family -----------------------------------------
// MODE 0: out = LN(x)
// MODE 1: out = LN(x + x2)                       (x2 has row stride D)
// MODE 2: out = LN(x) * silu(x2[row*ld2+off2+i]) (z-gate)
template<int VPT, int MODE>
__global__ void __launch_bounds__(256)
ln_kernel(const float* __restrict__ x, const float* __restrict__ x2,
          int ld2, int off2,
          const float* __restrict__ g, const float* __restrict__ b,
          float* __restrict__ out, int D, float eps)
{
    const int row = blockIdx.x;
    float v[VPT];
    float sx = 0.f, sq = 0.f;
    #pragma unroll
    for (int i = 0; i < VPT; i++) {
        int idx = threadIdx.x + i * 256;
        float t = x[(size_t)row * D + idx];
        if (MODE == 1) t += x2[(size_t)row * D + idx];
        v[i] = t; sx += t; sq += t * t;
    }
    float2 s = block_reduce2(sx, sq);
    float mu = s.x / (float)D;
    float var = s.y / (float)D - mu * mu;
    float rs = rsqrtf(var + eps);
    #pragma unroll
    for (int i = 0; i < VPT; i++) {
        int idx = threadIdx.x + i * 256;
        float o = (v[i] - mu) * rs * g[idx] + b[idx];
        if (MODE == 2) {
            float z = x2[(size_t)row * ld2 + off2 + idx];
            o *= z / (1.f + __expf(-z));
        }
        out[(size_t)row * D + idx] = o;
    }
}

// ---------------- generic NT GEMM: C[m,n] = sum_k A[m,k]*B[n,k] ------------
// EPI: 0 = store only, 1 = +bias, 2 = +bias then softplus, 3 = +bias +C (residual)
template<int BM, int BN, int BK, int TM, int TN, int EPI>
__global__ void __launch_bounds__((BM/TM)*(BN/TN))
gemm_nt(const float* __restrict__ A, int lda,
        const float* __restrict__ B, int ldb,
        const float* __restrict__ bias,
        float* __restrict__ C, int ldc,
        int kspan, long long sliceStride)
{
    constexpr int THREADS = (BM/TM)*(BN/TN);
    constexpr int AV = BK/4;
    constexpr int ASTEP = THREADS / AV;
    __shared__ float As[BK][BM+4];
    __shared__ float Bs[BK][BN+4];
    const int tid  = threadIdx.x;
    const int tCol = tid % (BN/TN);
    const int tRow = tid / (BN/TN);
    const int rowBase = blockIdx.y * BM;
    const int colBase = blockIdx.x * BN;
    const int kOff = blockIdx.z * kspan;
    float* Cz = C + (long long)blockIdx.z * sliceStride;

    const int aRow = tid / AV, aCol = tid % AV;

    float acc[TM][TN];
    #pragma unroll
    for (int i = 0; i < TM; i++)
        #pragma unroll
        for (int j = 0; j < TN; j++) acc[i][j] = 0.f;

    for (int kt = 0; kt < kspan; kt += BK) {
        const int kg = kOff + kt + aCol * 4;
        #pragma unroll
        for (int r = 0; r < BM; r += ASTEP) {
            int row = r + aRow;
            float4 v = *reinterpret_cast<const float4*>(&A[(size_t)(rowBase+row)*lda + kg]);
            As[aCol*4+0][row] = v.x; As[aCol*4+1][row] = v.y;
            As[aCol*4+2][row] = v.z; As[aCol*4+3][row] = v.w;
        }
        #pragma unroll
        for (int r = 0; r < BN; r += ASTEP) {
            int row = r + aRow;
            if ((BN % ASTEP == 0) || row < BN) {
                float4 v = *reinterpret_cast<const float4*>(&B[(size_t)(colBase+row)*ldb + kg]);
                Bs[aCol*4+0][row] = v.x; Bs[aCol*4+1][row] = v.y;
                Bs[aCol*4+2][row] = v.z; Bs[aCol*4+3][row] = v.w;
            }
        }
        __syncthreads();
        #pragma unroll
        for (int k = 0; k < BK; k++) {
            float rm[TM], rn[TN];
            #pragma unroll
            for (int i = 0; i < TM; i++) rm[i] = As[k][tRow*TM + i];
            #pragma unroll
            for (int j = 0; j < TN; j++) rn[j] = Bs[k][tCol*TN + j];
            #pragma unroll
            for (int i = 0; i < TM; i++)
                #pragma unroll
                for (int j = 0; j < TN; j++)
                    acc[i][j] = fmaf(rm[i], rn[j], acc[i][j]);
        }
        __syncthreads();
    }

    #pragma unroll
    for (int i = 0; i < TM; i++) {
        int row = rowBase + tRow*TM + i;
        #pragma unroll
        for (int j = 0; j < TN; j++) {
            int col = colBase + tCol*TN + j;
            float v = acc[i][j];
            if (EPI >= 1) v += bias[col];
            if (EPI == 2) v = fmaxf(v, 0.f) + log1pf(expf(-fabsf(v)));   // softplus
            size_t o = (size_t)row * ldc + col;
            if (EPI == 3) v += Cz[o];
            Cz[o] = v;
        }
    }
}

// ---------------- split-K reduce -------------------------------------------
__global__ void __launch_bounds__(256)
reduce_ks(const float* __restrict__ part, float* __restrict__ out, int n)
{
    int i = blockIdx.x * 256 + threadIdx.x;
    if (i < n) {
        float s = 0.f;
        #pragma unroll
        for (int z = 0; z < KSPLIT; z++) s += part[(size_t)z * n + i];
        out[i] = s;
    }
}

// ---------------- depthwise conv1d k=3, pad=1 ------------------------------
__global__ void __launch_bounds__(256)
conv_kernel(const float* __restrict__ xz, const float* __restrict__ w,
            const float* __restrict__ b, float* __restrict__ u)
{
    int idx = blockIdx.x * 256 + threadIdx.x;     // < SEQ*DI
    int d = idx & (DI - 1);
    int t = idx >> 11;
    float w0 = w[d*3+0], w1 = w[d*3+1], w2 = w[d*3+2];
    const float* col = xz + d;
    float xm = (t > 0)       ? col[(size_t)(t-1) * (2*DI)] : 0.f;
    float x0 =                 col[(size_t)t     * (2*DI)];
    float xp = (t < SEQ - 1) ? col[(size_t)(t+1) * (2*DI)] : 0.f;
    u[idx] = fmaf(w0, xm, fmaf(w1, x0, fmaf(w2, xp, b[d])));
}

// ---------------- scan helpers ---------------------------------------------
__device__ __forceinline__ void load_A_fast(const float* __restrict__ A_log, int d,
                                            float* a, bool& fast, float& a0)
{
    #pragma unroll
    for (int n = 0; n < NST; n++) a[n] = -__expf(A_log[(size_t)d * NST + n]);
    a0 = a[0];
    fast = true;
    #pragma unroll
    for (int n = 1; n < NST; n++)
        fast = fast && (fabsf(a[n] - (float)(n+1) * a0) <= 2e-5f * (float)(n+1));
}

// pass A: per-chunk local scan (h0 = 0) -> final state + product of dA
__global__ void __launch_bounds__(256)
scan_pass_a(const float* __restrict__ delta, const float* __restrict__ u,
            const float* __restrict__ dbc, const float* __restrict__ A_log,
            float* __restrict__ hl, float* __restrict__ pp)
{
    __shared__ float Bsh[CHUNK][NST];
    const int d = blockIdx.x * 256 + threadIdx.x;
    const int c = blockIdx.y;
    for (int i = threadIdx.x; i < CHUNK * NST; i += 256) {
        int t = i >> 4, n = i & 15;
        Bsh[t][n] = dbc[(size_t)(c*CHUNK + t) * 96 + 64 + n];
    }
    __syncthreads();

    float a[NST]; bool fast; float a0;
    load_A_fast(A_log, d, a, fast, a0);

    float h[NST], p[NST];
    #pragma unroll
    for (int n = 0; n < NST; n++) { h[n] = 0.f; p[n] = 1.f; }

    const int t0 = c * CHUNK;
    for (int t = 0; t < CHUNK; t++) {
        float dlt = delta[(size_t)(t0 + t) * DI + d];
        float uu  = u[(size_t)(t0 + t) * DI + d];
        float du  = dlt * uu;
        float dAv[NST];
        if (fast) {
            float e = __expf(dlt * a0);
            float w = e;
            #pragma unroll
            for (int n = 0; n < NST; n++) { dAv[n] = w; w *= e; }
        } else {
            #pragma unroll
            for (int n = 0; n < NST; n++) dAv[n] = __expf(dlt * a[n]);
        }
        #pragma unroll
        for (int n = 0; n < NST; n++) {
            h[n] = fmaf(dAv[n], h[n], du * Bsh[t][n]);
            p[n] *= dAv[n];
        }
    }
    #pragma unroll
    for (int n = 0; n < NST; n++) {
        size_t o = ((size_t)c * NST + n) * DI + d;
        hl[o] = h[n]; pp[o] = p[n];
    }
}

// pass B: sequential combine across chunks, per (d,n)
__global__ void __launch_bounds__(256)
scan_pass_b(const float* __restrict__ hl, const float* __restrict__ pp,
            float* __restrict__ h0)
{
    int i = blockIdx.x * 256 + threadIdx.x;   // over NST*DI
    if (i >= NST * DI) return;
    float h = 0.f;
    for (int c = 0; c < NCH; c++) {
        size_t idx = (size_t)c * NST * DI + i;
        h0[idx] = h;
        h = fmaf(pp[idx], h, hl[idx]);
    }
}

// pass C: replay with correct initial state, emit y
__global__ void __launch_bounds__(256)
scan_pass_c(const float* __restrict__ delta, const float* __restrict__ u,
            const float* __restrict__ dbc, const float* __restrict__ A_log,
            const float* __restrict__ Dp, const float* __restrict__ h0,
            float* __restrict__ y)
{
    __shared__ float Bsh[CHUNK][NST];
    __shared__ float Csh[CHUNK][NST];
    const int d = blockIdx.x * 256 + threadIdx.x;
    const int c = blockIdx.y;
    for (int i = threadIdx.x; i < CHUNK * NST; i += 256) {
        int t = i >> 4, n = i & 15;
        Bsh[t][n] = dbc[(size_t)(c*CHUNK + t) * 96 + 64 + n];
        Csh[t][n] = dbc[(size_t)(c*CHUNK + t) * 96 + 80 + n];
    }
    __syncthreads();

    float a[NST]; bool fast; float a0;
    load_A_fast(A_log, d, a, fast, a0);
    float Dv = Dp[d];

    float h[NST];
    #pragma unroll
    for (int n = 0; n < NST; n++) h[n] = h0[((size_t)c * NST + n) * DI + d];

    const int t0 = c * CHUNK;
    for (int t = 0; t < CHUNK; t++) {
        float dlt = delta[(size_t)(t0 + t) * DI + d];
        float uu  = u[(size_t)(t0 + t) * DI + d];
        float du  = dlt * uu;
        float dAv[NST];
        if (fast) {
            float e = __expf(dlt * a0);
            float w = e;
            #pragma unroll
            for (int n = 0; n < NST; n++) { dAv[n] = w; w *= e; }
        } else {
            #pragma unroll
            for (int n = 0; n < NST; n++) dAv[n] = __expf(dlt * a[n]);
        }
        float yv = 0.f;
        #pragma unroll
        for (int n = 0; n < NST; n++) {
            h[n] = fmaf(dAv[n], h[n], du * Bsh[t][n]);
            yv = fmaf(h[n], Csh[t][n], yv);
        }
        y[(size_t)(t0 + t) * DI + d] = fmaf(Dv, uu, yv);
    }
}

// ---------------- host ------------------------------------------------------
extern "C" void kernel_launch(void* const* d_in, const int* in_sizes, int n_in,
                              void* d_out, int out_size)
{
    const float* x         = (const float*)d_in[0];
    const float* pos_enc   = (const float*)d_in[1];
    const float* ln_g      = (const float*)d_in[2];
    const float* ln_b      = (const float*)d_in[3];
    const float* innorm_g  = (const float*)d_in[4];
    const float* innorm_b  = (const float*)d_in[5];
    const float* in_proj_w = (const float*)d_in[6];
    const float* in_proj_b = (const float*)d_in[7];
    const float* conv_w    = (const float*)d_in[8];
    const float* conv_b    = (const float*)d_in[9];
    const float* deltaBC_w = (const float*)d_in[10];
    const float* dt_proj_w = (const float*)d_in[11];
    const float* dt_proj_b = (const float*)d_in[12];
    const float* A_log     = (const float*)d_in[13];
    const float* Dp        = (const float*)d_in[14];
    const float* outnorm_g = (const float*)d_in[15];
    const float* outnorm_b = (const float*)d_in[16];
    const float* out_proj_w= (const float*)d_in[17];
    const float* out_proj_b= (const float*)d_in[18];

    float *enc, *hbuf, *xz, *u, *dbcp, *dbc, *delta, *y, *y2, *hl, *pp, *h0;
    cudaGetSymbolAddress((void**)&enc,   g_enc);
    cudaGetSymbolAddress((void**)&hbuf,  g_hbuf);
    cudaGetSymbolAddress((void**)&xz,    g_xz);
    cudaGetSymbolAddress((void**)&u,     g_u);
    cudaGetSymbolAddress((void**)&dbcp,  g_dbcp);
    cudaGetSymbolAddress((void**)&dbc,   g_dbc);
    cudaGetSymbolAddress((void**)&delta, g_delta);
    cudaGetSymbolAddress((void**)&y,     g_y);
    cudaGetSymbolAddress((void**)&y2,    g_y2);
    cudaGetSymbolAddress((void**)&hl,    g_hl);
    cudaGetSymbolAddress((void**)&pp,    g_pp);
    cudaGetSymbolAddress((void**)&h0,    g_h0);

    // pre-encoder: enc = LN(x + pos_enc), eps=1e-6
    ln_kernel<4,1><<<SEQ, 256>>>(x, pos_enc, DM, 0, ln_g, ln_b, enc, DM, 1e-6f);

    for (int l = 0; l < NL; l++) {
        // 1) h = LN(enc)
        ln_kernel<4,0><<<SEQ, 256>>>(enc, nullptr, 0, 0,
                                     innorm_g + (size_t)l*DM, innorm_b + (size_t)l*DM,
                                     hbuf, DM, 1e-5f);
        // 2) xz = h @ in_proj_w^T + b  : M=4096 N=4096 K=1024
        gemm_nt<128,128,16,8,8,1><<<dim3(2*DI/128, SEQ/128, 1), 256>>>(
            hbuf, DM, in_proj_w + (size_t)l*2*DI*DM, DM,
            in_proj_b + (size_t)l*2*DI, xz, 2*DI, DM, 0);
        // 3) depthwise conv -> u
        conv_kernel<<<SEQ*DI/256, 256>>>(xz, conv_w + (size_t)l*DI*3,
                                         conv_b + (size_t)l*DI, u);
        // 4) dbc = u @ deltaBC_w^T : M=4096 N=96 K=2048, split-K=8
        gemm_nt<64,96,16,4,6,0><<<dim3(1, SEQ/64, KSPLIT), 256>>>(
            u, DI, deltaBC_w + (size_t)l*96*DI, DI,
            nullptr, dbcp, 96, DI/KSPLIT, (long long)SEQ*96);
        reduce_ks<<<(SEQ*96 + 255)/256, 256>>>(dbcp, dbc, SEQ*96);
        // 5) delta = softplus(dbc[:, :64] @ dt_proj_w^T + b) : M=4096 N=2048 K=64
        gemm_nt<128,128,16,8,8,2><<<dim3(DI/128, SEQ/128, 1), 256>>>(
            dbc, 96, dt_proj_w + (size_t)l*DI*64, 64,
            dt_proj_b + (size_t)l*DI, delta, DI, 64, 0);
        // 6) chunked selective scan
        scan_pass_a<<<dim3(DI/256, NCH), 256>>>(delta, u, dbc,
                                                A_log + (size_t)l*DI*NST, hl, pp);
        scan_pass_b<<<(NST*DI)/256, 256>>>(hl, pp, h0);
        scan_pass_c<<<dim3(DI/256, NCH), 256>>>(delta, u, dbc,
                                                A_log + (size_t)l*DI*NST,
                                                Dp + (size_t)l*DI, h0, y);
        // 7) y2 = LN(y) * silu(z)
        ln_kernel<8,2><<<SEQ, 256>>>(y, xz, 2*DI, DI,
                                     outnorm_g + (size_t)l*DI, outnorm_b + (size_t)l*DI,
                                     y2, DI, 1e-5f);
        // 8) enc = y2 @ out_proj_w^T + b + enc : M=4096 N=1024 K=2048
        gemm_nt<128,128,16,8,8,3><<<dim3(DM/128, SEQ/128, 1), 256>>>(
            y2, DI, out_proj_w + (size_t)l*DM*DI, DI,
            out_proj_b + (size_t)l*DM, enc, DM, DI, 0);
    }

    cudaMemcpyAsync(d_out, enc, sizeof(float) * (size_t)out_size,
                    cudaMemcpyDeviceToDevice);
}

// round 9
// speedup vs baseline: 1.0557x; 1.0557x over previous
#include <cuda_runtime.h>
#include <cuda_bf16.h>
#include <cstdint>
#include <math.h>

#define SEQ   4096
#define DM    1024
#define DI    2048
#define NST   16
#define NL    4
#define NCH   64
#define CHUNK 64

// ---------------- scratch (device globals; no allocation allowed) ----------
__device__ float g_enc[SEQ*DM];
__device__ float g_xz[SEQ*2*DI];
__device__ float g_u[SEQ*DI];
__device__ float g_dbc[SEQ*96];
__device__ float g_delta[SEQ*DI];
__device__ float g_y[SEQ*DI];
__device__ float g_hl[NCH*NST*DI];
__device__ float g_pp[NCH*NST*DI];
__device__ float g_h0[NCH*NST*DI];
// bf16 split activations (A' = [hi | lo | hi] along K)
__device__ __nv_bfloat16 g_hbufs[SEQ*3*DM];
__device__ __nv_bfloat16 g_us[SEQ*3*DI];
__device__ __nv_bfloat16 g_dbcs[SEQ*3*64];
__device__ __nv_bfloat16 g_y2s[SEQ*3*DI];
// bf16 split weights (B' = [hi | hi | lo] along K)
__device__ __nv_bfloat16 g_win[NL*(2*DI)*(3*DM)];
__device__ __nv_bfloat16 g_wdbc[NL*128*(3*DI)];   // padded 96->128 rows (pad stays 0)
__device__ __nv_bfloat16 g_wdt[NL*DI*(3*64)];
__device__ __nv_bfloat16 g_wout[NL*DM*(3*DI)];

// ======================= helpers ============================================
__device__ __forceinline__ unsigned int smem_u32(const void* smem_ptr) {
    unsigned int addr;
    asm("{ .reg .u64 tmp; cvta.to.shared.u64 tmp, %1; cvt.u32.u64 %0, tmp; }"
        : "=r"(addr) : "l"(smem_ptr));
    return addr;
}

#define SMEM_SWIZZLE_128B(byte_offset) \
    ((byte_offset) ^ (((byte_offset) >> 3) & 0x70))

#define LDSM_X4(r0, r1, r2, r3, addr) \
    asm volatile( \
        "ldmatrix.sync.aligned.m8n8.x4.shared.b16 {%0, %1, %2, %3}, [%4];" \
        : "=r"(r0), "=r"(r1), "=r"(r2), "=r"(r3) : "r"(addr))

#define MMA16816(c, a, b) \
    asm volatile( \
        "mma.sync.aligned.m16n8k16.row.col.f32.bf16.bf16.f32 " \
        "{%0, %1, %2, %3}, {%4, %5, %6, %7}, {%8, %9}, {%0, %1, %2, %3};" \
        : "+f"((c)[0]), "+f"((c)[1]), "+f"((c)[2]), "+f"((c)[3]) \
        : "r"((a)[0]), "r"((a)[1]), "r"((a)[2]), "r"((a)[3]), \
          "r"((b)[0]), "r"((b)[1]))

// ======================= bf16 mma.sync GEMM (NT) ============================
// C[m,n] = sum_k A'[m,k] * B'[n,k].  A': [M,Kp] bf16, B': [Npad,Kp] bf16.
// Kp % 64 == 0. 128x128 CTA tile, 256 threads (8 warps = 2m x 4n),
// warp tile 64x32, K chunks of 64 in SW128-swizzled smem, ldmatrix + HMMA.
// EPI: 0 store (masked to Nact), 1 +bias, 2 +bias->softplus, 3 +bias +C
template<int EPI>
__global__ void __launch_bounds__(256)
gemm_mma(const __nv_bfloat16* __restrict__ A, int lda,
         const __nv_bfloat16* __restrict__ B, int ldb,
         const float* __restrict__ bias,
         float* __restrict__ C, int ldc, int Kp, int Nact)
{
    __shared__ __align__(128) __nv_bfloat16 As[128 * 64];
    __shared__ __align__(128) __nv_bfloat16 Bs[128 * 64];

    const int tid  = threadIdx.x;
    const int wid  = tid >> 5;
    const int lane = tid & 31;
    const int wm   = wid >> 2;        // 0..1
    const int wn   = wid & 3;         // 0..3
    const int rowBase = blockIdx.y * 128;
    const int colBase = blockIdx.x * 128;
    const int nch = Kp >> 6;

    const unsigned int sA = smem_u32(As);
    const unsigned int sB = smem_u32(Bs);
    char* As_b = (char*)As;
    char* Bs_b = (char*)Bs;

    float acc[4][4][4];
    #pragma unroll
    for (int mf = 0; mf < 4; mf++)
        #pragma unroll
        for (int nf = 0; nf < 4; nf++)
            #pragma unroll
            for (int r = 0; r < 4; r++) acc[mf][nf][r] = 0.f;

    // ldmatrix per-lane row/k offsets
    const int aRow  = (lane & 7) + ((lane >> 3) & 1) * 8;   // row within 16
    const int aKofs = (lane >> 4) * 8;                       // 0 or 8
    const int bRow  = (lane & 7) + ((lane >> 4) & 1) * 8;
    const int bKofs = ((lane >> 3) & 1) * 8;

    const __nv_bfloat16* Atile = A + (size_t)rowBase * lda;
    const __nv_bfloat16* Btile = B + (size_t)colBase * ldb;

    for (int c = 0; c < nch; c++) {
        // ---- load 128x64 bf16 tiles to swizzled smem ----
        #pragma unroll
        for (int i = 0; i < 4; i++) {
            int unit = tid + i * 256;          // 0..1023
            int r = unit >> 3;
            int uc = unit & 7;
            unsigned int so = SMEM_SWIZZLE_128B((unsigned int)(r * 128 + uc * 16));
            uint4 va = *(const uint4*)(Atile + (size_t)r * lda + c * 64 + uc * 8);
            uint4 vb = *(const uint4*)(Btile + (size_t)r * ldb + c * 64 + uc * 8);
            *(uint4*)(As_b + so) = va;
            *(uint4*)(Bs_b + so) = vb;
        }
        __syncthreads();

        // ---- 4 k-steps of 16 ----
        #pragma unroll
        for (int ks = 0; ks < 4; ks++) {
            const int kk = ks * 16;
            unsigned int afr[4][4];
            unsigned int bfr[4][2];
            #pragma unroll
            for (int mf = 0; mf < 4; mf++) {
                unsigned int off = (unsigned int)(
                    (wm * 64 + mf * 16 + aRow) * 128 + (kk + aKofs) * 2);
                unsigned int ad = sA + SMEM_SWIZZLE_128B(off);
                LDSM_X4(afr[mf][0], afr[mf][1], afr[mf][2], afr[mf][3], ad);
            }
            #pragma unroll
            for (int bp = 0; bp < 2; bp++) {
                unsigned int off = (unsigned int)(
                    (wn * 32 + bp * 16 + bRow) * 128 + (kk + bKofs) * 2);
                unsigned int bd = sB + SMEM_SWIZZLE_128B(off);
                LDSM_X4(bfr[bp*2][0], bfr[bp*2][1],
                        bfr[bp*2+1][0], bfr[bp*2+1][1], bd);
            }
            #pragma unroll
            for (int mf = 0; mf < 4; mf++)
                #pragma unroll
                for (int nf = 0; nf < 4; nf++)
                    MMA16816(acc[mf][nf], afr[mf], bfr[nf]);
        }
        __syncthreads();
    }

    // ---- epilogue ----
    #pragma unroll
    for (int mf = 0; mf < 4; mf++) {
        int r0 = rowBase + wm * 64 + mf * 16 + (lane >> 2);
        #pragma unroll
        for (int nf = 0; nf < 4; nf++) {
            int c0 = colBase + wn * 32 + nf * 8 + (lane & 3) * 2;
            if (c0 < Nact) {
                float v0 = acc[mf][nf][0];
                float v1 = acc[mf][nf][1];
                float v2 = acc[mf][nf][2];
                float v3 = acc[mf][nf][3];
                if (EPI >= 1) {
                    float b0 = bias[c0];
                    float b1 = bias[c0 + 1];
                    v0 += b0; v1 += b1; v2 += b0; v3 += b1;
                }
                if (EPI == 2) {
                    v0 = fmaxf(v0, 0.f) + log1pf(expf(-fabsf(v0)));
                    v1 = fmaxf(v1, 0.f) + log1pf(expf(-fabsf(v1)));
                    v2 = fmaxf(v2, 0.f) + log1pf(expf(-fabsf(v2)));
                    v3 = fmaxf(v3, 0.f) + log1pf(expf(-fabsf(v3)));
                }
                size_t o0 = (size_t)r0 * ldc + c0;
                size_t o1 = (size_t)(r0 + 8) * ldc + c0;
                if (EPI == 3) {
                    v0 += C[o0]; v1 += C[o0 + 1];
                    v2 += C[o1]; v3 += C[o1 + 1];
                }
                C[o0] = v0; C[o0 + 1] = v1;
                C[o1] = v2; C[o1 + 1] = v3;
            }
        }
    }
}

// ======================= split conversion =================================
__device__ __forceinline__ void split2(float v, __nv_bfloat16& hi, __nv_bfloat16& lo) {
    hi = __float2bfloat16(v);
    lo = __float2bfloat16(v - __bfloat162float(hi));
}

// weights: B' = [hi | hi | lo]
__global__ void __launch_bounds__(256)
wsplit(const float* __restrict__ W, __nv_bfloat16* __restrict__ out, int N, int K)
{
    int i = blockIdx.x * 256 + threadIdx.x;
    if (i >= N * K) return;
    int n = i / K;
    int k = i - n * K;
    __nv_bfloat16 hi, lo;
    split2(W[i], hi, lo);
    size_t b = (size_t)n * 3 * K;
    out[b + k] = hi;
    out[b + K + k] = hi;
    out[b + 2 * K + k] = lo;
}

// dbc cols [0,64) -> A' split [SEQ,192]
__global__ void __launch_bounds__(256)
split_dbc(const float* __restrict__ dbc, __nv_bfloat16* __restrict__ out)
{
    int i = blockIdx.x * 256 + threadIdx.x;
    if (i >= SEQ * 64) return;
    int row = i >> 6;
    int col = i & 63;
    __nv_bfloat16 hi, lo;
    split2(dbc[row * 96 + col], hi, lo);
    size_t b = (size_t)row * 192;
    out[b + col] = hi;
    out[b + 64 + col] = lo;
    out[b + 128 + col] = hi;
}

// ---------------- block reduce (sum, sumsq) --------------------------------
__device__ __forceinline__ float2 block_reduce2(float sx, float sq) {
    __shared__ float shx[8];
    __shared__ float shq[8];
    const unsigned m = 0xffffffffu;
    #pragma unroll
    for (int o = 16; o > 0; o >>= 1) {
        sx += __shfl_xor_sync(m, sx, o);
        sq += __shfl_xor_sync(m, sq, o);
    }
    int w = threadIdx.x >> 5;
    if ((threadIdx.x & 31) == 0) { shx[w] = sx; shq[w] = sq; }
    __syncthreads();
    if (threadIdx.x == 0) {
        float ax = 0.f;
        float aq = 0.f;
        #pragma unroll
        for (int i = 0; i < 8; i++) { ax += shx[i]; aq += shq[i]; }
        shx[0] = ax;
        shq[0] = aq;
    }
    __syncthreads();
    return make_float2(shx[0], shq[0]);
}

// ---------------- layernorm family -----------------------------------------
// MODE 0: LN(x); MODE 1: LN(x+x2); MODE 2: LN(x)*silu(x2[row*ld2+off2+i])
// SPLITK==0: write fp32 to outf; SPLITK>0: write bf16 split [hi|lo|hi] to outs
template<int VPT, int MODE, int SPLITK>
__global__ void __launch_bounds__(256)
ln_kernel(const float* __restrict__ x, const float* __restrict__ x2,
          int ld2, int off2,
          const float* __restrict__ g, const float* __restrict__ b,
          float* __restrict__ outf, __nv_bfloat16* __restrict__ outs,
          int D, float eps)
{
    const int row = blockIdx.x;
    float v[VPT];
    float sx = 0.f;
    float sq = 0.f;
    #pragma unroll
    for (int i = 0; i < VPT; i++) {
        int idx = threadIdx.x + i * 256;
        float t = x[(size_t)row * D + idx];
        if (MODE == 1) t += x2[(size_t)row * D + idx];
        v[i] = t;
        sx += t;
        sq += t * t;
    }
    float2 s = block_reduce2(sx, sq);
    float mu = s.x / (float)D;
    float var = s.y / (float)D - mu * mu;
    float rs = rsqrtf(var + eps);
    #pragma unroll
    for (int i = 0; i < VPT; i++) {
        int idx = threadIdx.x + i * 256;
        float o = (v[i] - mu) * rs * g[idx] + b[idx];
        if (MODE == 2) {
            float z = x2[(size_t)row * ld2 + off2 + idx];
            o *= z / (1.f + __expf(-z));
        }
        if (SPLITK == 0) {
            outf[(size_t)row * D + idx] = o;
        } else {
            __nv_bfloat16 hi, lo;
            split2(o, hi, lo);
            size_t rb = (size_t)row * 3 * SPLITK;
            outs[rb + idx] = hi;
            outs[rb + SPLITK + idx] = lo;
            outs[rb + 2 * SPLITK + idx] = hi;
        }
    }
}

// ---------------- depthwise conv1d k=3, pad=1 (+ bf16 split of u) ----------
__global__ void __launch_bounds__(256)
conv_kernel(const float* __restrict__ xz, const float* __restrict__ w,
            const float* __restrict__ b, float* __restrict__ u,
            __nv_bfloat16* __restrict__ usplit)
{
    int idx = blockIdx.x * 256 + threadIdx.x;     // < SEQ*DI
    int d = idx & (DI - 1);
    int t = idx >> 11;
    float w0 = w[d*3+0];
    float w1 = w[d*3+1];
    float w2 = w[d*3+2];
    const float* col = xz + d;
    float xm = (t > 0)       ? col[(size_t)(t-1) * (2*DI)] : 0.f;
    float x0 =                 col[(size_t)t     * (2*DI)];
    float xp = (t < SEQ - 1) ? col[(size_t)(t+1) * (2*DI)] : 0.f;
    float v = fmaf(w0, xm, fmaf(w1, x0, fmaf(w2, xp, b[d])));
    u[idx] = v;
    __nv_bfloat16 hi, lo;
    split2(v, hi, lo);
    size_t rb = (size_t)t * 3 * DI;
    usplit[rb + d] = hi;
    usplit[rb + DI + d] = lo;
    usplit[rb + 2 * DI + d] = hi;
}

// ---------------- scan helpers ---------------------------------------------
__device__ __forceinline__ void load_A_fast(const float* __restrict__ A_log, int d,
                                            float* a, bool& fast, float& a0)
{
    #pragma unroll
    for (int n = 0; n < NST; n++) a[n] = -__expf(A_log[(size_t)d * NST + n]);
    a0 = a[0];
    fast = true;
    #pragma unroll
    for (int n = 1; n < NST; n++)
        fast = fast && (fabsf(a[n] - (float)(n+1) * a0) <= 2e-5f * (float)(n+1));
}

__global__ void __launch_bounds__(256)
scan_pass_a(const float* __restrict__ delta, const float* __restrict__ u,
            const float* __restrict__ dbc, const float* __restrict__ A_log,
            float* __restrict__ hl, float* __restrict__ pp)
{
    __shared__ float Bsh[CHUNK][NST];
    const int d = blockIdx.x * 256 + threadIdx.x;
    const int c = blockIdx.y;
    for (int i = threadIdx.x; i < CHUNK * NST; i += 256) {
        int t = i >> 4;
        int n = i & 15;
        Bsh[t][n] = dbc[(size_t)(c*CHUNK + t) * 96 + 64 + n];
    }
    __syncthreads();

    float a[NST];
    bool fast;
    float a0;
    load_A_fast(A_log, d, a, fast, a0);

    float h[NST];
    float p[NST];
    #pragma unroll
    for (int n = 0; n < NST; n++) { h[n] = 0.f; p[n] = 1.f; }

    const int t0 = c * CHUNK;
    for (int t = 0; t < CHUNK; t++) {
        float dlt = delta[(size_t)(t0 + t) * DI + d];
        float uu  = u[(size_t)(t0 + t) * DI + d];
        float du  = dlt * uu;
        float dAv[NST];
        if (fast) {
            float e = __expf(dlt * a0);
            float w = e;
            #pragma unroll
            for (int n = 0; n < NST; n++) { dAv[n] = w; w *= e; }
        } else {
            #pragma unroll
            for (int n = 0; n < NST; n++) dAv[n] = __expf(dlt * a[n]);
        }
        #pragma unroll
        for (int n = 0; n < NST; n++) {
            h[n] = fmaf(dAv[n], h[n], du * Bsh[t][n]);
            p[n] *= dAv[n];
        }
    }
    #pragma unroll
    for (int n = 0; n < NST; n++) {
        size_t o = ((size_t)c * NST + n) * DI + d;
        hl[o] = h[n];
        pp[o] = p[n];
    }
}

__global__ void __launch_bounds__(256)
scan_pass_b(const float* __restrict__ hl, const float* __restrict__ pp,
            float* __restrict__ h0)
{
    int i = blockIdx.x * 256 + threadIdx.x;
    if (i >= NST * DI) return;
    float h = 0.f;
    for (int c = 0; c < NCH; c++) {
        size_t idx = (size_t)c * NST * DI + i;
        h0[idx] = h;
        h = fmaf(pp[idx], h, hl[idx]);
    }
}

__global__ void __launch_bounds__(256)
scan_pass_c(const float* __restrict__ delta, const float* __restrict__ u,
            const float* __restrict__ dbc, const float* __restrict__ A_log,
            const float* __restrict__ Dp, const float* __restrict__ h0,
            float* __restrict__ y)
{
    __shared__ float Bsh[CHUNK][NST];
    __shared__ float Csh[CHUNK][NST];
    const int d = blockIdx.x * 256 + threadIdx.x;
    const int c = blockIdx.y;
    for (int i = threadIdx.x; i < CHUNK * NST; i += 256) {
        int t = i >> 4;
        int n = i & 15;
        Bsh[t][n] = dbc[(size_t)(c*CHUNK + t) * 96 + 64 + n];
        Csh[t][n] = dbc[(size_t)(c*CHUNK + t) * 96 + 80 + n];
    }
    __syncthreads();

    float a[NST];
    bool fast;
    float a0;
    load_A_fast(A_log, d, a, fast, a0);
    float Dv = Dp[d];

    float h[NST];
    #pragma unroll
    for (int n = 0; n < NST; n++) h[n] = h0[((size_t)c * NST + n) * DI + d];

    const int t0 = c * CHUNK;
    for (int t = 0; t < CHUNK; t++) {
        float dlt = delta[(size_t)(t0 + t) * DI + d];
        float uu  = u[(size_t)(t0 + t) * DI + d];
        float du  = dlt * uu;
        float dAv[NST];
        if (fast) {
            float e = __expf(dlt * a0);
            float w = e;
            #pragma unroll
            for (int n = 0; n < NST; n++) { dAv[n] = w; w *= e; }
        } else {
            #pragma unroll
            for (int n = 0; n < NST; n++) dAv[n] = __expf(dlt * a[n]);
        }
        float yv = 0.f;
        #pragma unroll
        for (int n = 0; n < NST; n++) {
            h[n] = fmaf(dAv[n], h[n], du * Bsh[t][n]);
            yv = fmaf(h[n], Csh[t][n], yv);
        }
        y[(size_t)(t0 + t) * DI + d] = fmaf(Dv, uu, yv);
    }
}

// ---------------- host ------------------------------------------------------
extern "C" void kernel_launch(void* const* d_in, const int* in_sizes, int n_in,
                              void* d_out, int out_size)
{
    const float* x         = (const float*)d_in[0];
    const float* pos_enc   = (const float*)d_in[1];
    const float* ln_g      = (const float*)d_in[2];
    const float* ln_b      = (const float*)d_in[3];
    const float* innorm_g  = (const float*)d_in[4];
    const float* innorm_b  = (const float*)d_in[5];
    const float* in_proj_w = (const float*)d_in[6];
    const float* in_proj_b = (const float*)d_in[7];
    const float* conv_w    = (const float*)d_in[8];
    const float* conv_b    = (const float*)d_in[9];
    const float* deltaBC_w = (const float*)d_in[10];
    const float* dt_proj_w = (const float*)d_in[11];
    const float* dt_proj_b = (const float*)d_in[12];
    const float* A_log     = (const float*)d_in[13];
    const float* Dp        = (const float*)d_in[14];
    const float* outnorm_g = (const float*)d_in[15];
    const float* outnorm_b = (const float*)d_in[16];
    const float* out_proj_w= (const float*)d_in[17];
    const float* out_proj_b= (const float*)d_in[18];

    float* enc = 0;
    float* xz = 0;
    float* u = 0;
    float* dbc = 0;
    float* delta = 0;
    float* y = 0;
    float* hl = 0;
    float* pp = 0;
    float* h0 = 0;
    __nv_bfloat16* hbufs = 0;
    __nv_bfloat16* usplit = 0;
    __nv_bfloat16* dbcs = 0;
    __nv_bfloat16* y2s = 0;
    __nv_bfloat16* win = 0;
    __nv_bfloat16* wdbc = 0;
    __nv_bfloat16* wdt = 0;
    __nv_bfloat16* wout = 0;
    cudaGetSymbolAddress((void**)&enc,   g_enc);
    cudaGetSymbolAddress((void**)&xz,    g_xz);
    cudaGetSymbolAddress((void**)&u,     g_u);
    cudaGetSymbolAddress((void**)&dbc,   g_dbc);
    cudaGetSymbolAddress((void**)&delta, g_delta);
    cudaGetSymbolAddress((void**)&y,     g_y);
    cudaGetSymbolAddress((void**)&hl,    g_hl);
    cudaGetSymbolAddress((void**)&pp,    g_pp);
    cudaGetSymbolAddress((void**)&h0,    g_h0);
    cudaGetSymbolAddress((void**)&hbufs, g_hbufs);
    cudaGetSymbolAddress((void**)&usplit,g_us);
    cudaGetSymbolAddress((void**)&dbcs,  g_dbcs);
    cudaGetSymbolAddress((void**)&y2s,   g_y2s);
    cudaGetSymbolAddress((void**)&win,   g_win);
    cudaGetSymbolAddress((void**)&wdbc,  g_wdbc);
    cudaGetSymbolAddress((void**)&wdt,   g_wdt);
    cudaGetSymbolAddress((void**)&wout,  g_wout);

    // weight splits (recomputed every call — determinism)
    {
        int n1 = NL * 2*DI * DM;
        wsplit<<<(n1+255)/256, 256>>>(in_proj_w, win, NL*2*DI, DM);
        int n2 = NL * DM * DI;
        wsplit<<<(n2+255)/256, 256>>>(out_proj_w, wout, NL*DM, DI);
        int n3 = NL * DI * 64;
        wsplit<<<(n3+255)/256, 256>>>(dt_proj_w, wdt, NL*DI, 64);
        for (int l = 0; l < NL; l++) {
            int n4 = 96 * DI;
            wsplit<<<(n4+255)/256, 256>>>(deltaBC_w + (size_t)l*96*DI,
                                          wdbc + (size_t)l*128*3*DI, 96, DI);
        }
    }

    // pre-encoder: enc = LN(x + pos_enc), eps=1e-6
    ln_kernel<4,1,0><<<SEQ, 256>>>(x, pos_enc, DM, 0, ln_g, ln_b, enc, (__nv_bfloat16*)0, DM, 1e-6f);

    for (int l = 0; l < NL; l++) {
        // 1) hbufs = split(LN(enc))
        ln_kernel<4,0,DM><<<SEQ, 256>>>(enc, (const float*)0, 0, 0,
                                        innorm_g + (size_t)l*DM, innorm_b + (size_t)l*DM,
                                        (float*)0, hbufs, DM, 1e-5f);
        // 2) xz = hbuf @ in_proj_w^T + b  (M=4096 N=4096 K'=3072)
        gemm_mma<1><<<dim3(2*DI/128, SEQ/128), 256>>>(
            hbufs, 3*DM, win + (size_t)l*2*DI*3*DM, 3*DM,
            in_proj_b + (size_t)l*2*DI, xz, 2*DI, 3*DM, 2*DI);
        // 3) depthwise conv -> u (+split)
        conv_kernel<<<SEQ*DI/256, 256>>>(xz, conv_w + (size_t)l*DI*3,
                                         conv_b + (size_t)l*DI, u, usplit);
        // 4) dbc = u @ deltaBC_w^T (N=96 padded to 128 tile, K'=6144)
        gemm_mma<0><<<dim3(1, SEQ/128), 256>>>(
            usplit, 3*DI, wdbc + (size_t)l*128*3*DI, 3*DI,
            (const float*)0, dbc, 96, 3*DI, 96);
        split_dbc<<<SEQ*64/256, 256>>>(dbc, dbcs);
        // 5) delta = softplus(dbc[:,:64] @ dt_proj_w^T + b)  (K'=192)
        gemm_mma<2><<<dim3(DI/128, SEQ/128), 256>>>(
            dbcs, 192, wdt + (size_t)l*DI*192, 192,
            dt_proj_b + (size_t)l*DI, delta, DI, 192, DI);
        // 6) chunked selective scan
        scan_pass_a<<<dim3(DI/256, NCH), 256>>>(delta, u, dbc,
                                                A_log + (size_t)l*DI*NST, hl, pp);
        scan_pass_b<<<(NST*DI)/256, 256>>>(hl, pp, h0);
        scan_pass_c<<<dim3(DI/256, NCH), 256>>>(delta, u, dbc,
                                                A_log + (size_t)l*DI*NST,
                                                Dp + (size_t)l*DI, h0, y);
        // 7) y2s = split(LN(y) * silu(z))
        ln_kernel<8,2,DI><<<SEQ, 256>>>(y, xz, 2*DI, DI,
                                        outnorm_g + (size_t)l*DI, outnorm_b + (size_t)l*DI,
                                        (float*)0, y2s, DI, 1e-5f);
        // 8) enc = y2 @ out_proj_w^T + b + enc  (K'=6144)
        gemm_mma<3><<<dim3(DM/128, SEQ/128), 256>>>(
            y2s, 3*DI, wout + (size_t)l*DM*3*DI, 3*DI,
            out_proj_b + (size_t)l*DM, enc, DM, 3*DI, DM);
    }

    cudaMemcpyAsync(d_out, enc, sizeof(float) * (size_t)out_size,
                    cudaMemcpyDeviceToDevice);
}

// round 11
// speedup vs baseline: 1.5620x; 1.4795x over previous
#include <cuda_runtime.h>
#include <cuda_bf16.h>
#include <cstdint>
#include <math.h>

#define SEQ   4096
#define DM    1024
#define DI    2048
#define NST   16
#define NL    4
#define NCH   64
#define CHUNK 64

// ---------------- scratch (device globals; no allocation allowed) ----------
__device__ float g_enc[SEQ*DM];
__device__ float g_xz[SEQ*2*DI];
__device__ float g_u[SEQ*DI];
__device__ float g_dbc[SEQ*96];
__device__ float g_delta[SEQ*DI];
__device__ float g_y[SEQ*DI];
__device__ float g_hl[NCH*NST*DI];
__device__ float g_pp[NCH*NST*DI];
__device__ float g_h0[NCH*NST*DI];
// bf16 split activations (A' = [hi | lo | hi] along K)
__device__ __nv_bfloat16 g_hbufs[SEQ*3*DM];
__device__ __nv_bfloat16 g_us[SEQ*3*DI];
__device__ __nv_bfloat16 g_dbcs[SEQ*3*64];
__device__ __nv_bfloat16 g_y2s[SEQ*3*DI];
// bf16 split weights (B' = [hi | hi | lo] along K)
__device__ __nv_bfloat16 g_win[NL*(2*DI)*(3*DM)];
__device__ __nv_bfloat16 g_wdbc[NL*128*(3*DI)];   // padded 96->128 rows (pad stays 0)
__device__ __nv_bfloat16 g_wdt[NL*DI*(3*64)];
__device__ __nv_bfloat16 g_wout[NL*DM*(3*DI)];

// ======================= helpers ============================================
__device__ __forceinline__ unsigned int smem_u32(const void* smem_ptr) {
    unsigned int addr;
    asm("{ .reg .u64 tmp; cvta.to.shared.u64 tmp, %1; cvt.u32.u64 %0, tmp; }"
        : "=r"(addr) : "l"(smem_ptr));
    return addr;
}

#define LDSM_X4(r0, r1, r2, r3, addr) \
    asm volatile( \
        "ldmatrix.sync.aligned.m8n8.x4.shared.b16 {%0, %1, %2, %3}, [%4];" \
        : "=r"(r0), "=r"(r1), "=r"(r2), "=r"(r3) : "r"(addr))

#define MMA16816(c, a, b) \
    asm volatile( \
        "mma.sync.aligned.m16n8k16.row.col.f32.bf16.bf16.f32 " \
        "{%0, %1, %2, %3}, {%4, %5, %6, %7}, {%8, %9}, {%0, %1, %2, %3};" \
        : "+f"((c)[0]), "+f"((c)[1]), "+f"((c)[2]), "+f"((c)[3]) \
        : "r"((a)[0]), "r"((a)[1]), "r"((a)[2]), "r"((a)[3]), \
          "r"((b)[0]), "r"((b)[1]))

#define CP_ASYNC16(dst, src) \
    asm volatile("cp.async.cg.shared.global [%0], [%1], 16;" \
                 :: "r"(dst), "l"(src) : "memory")
#define CP_COMMIT() \
    asm volatile("cp.async.commit_group;" ::: "memory")
#define CP_WAIT1() \
    asm volatile("cp.async.wait_group 1;" ::: "memory")

// ======================= bf16 mma.sync GEMM (NT), cp.async pipelined ========
// C[m,n] = sum_k A'[m,k] * B'[n,k].  A': [M,Kp] bf16, B': [Npad,Kp] bf16.
// Kp % 32 == 0. 128x128 CTA tile, 256 threads (8 warps = 2m x 4n, warp 64x32).
// K chunks of 32; 3 smem stages (16KB each, 48KB total); cp.async pipeline.
// smem rows are 64B; swizzle: 16B-unit col ^= (row & 3)  (max 2-way LDSM).
// EPI: 0 store (masked to Nact), 1 +bias, 2 +bias->softplus, 3 +bias +C
template<int EPI>
__global__ void __launch_bounds__(256)
gemm_mma(const __nv_bfloat16* __restrict__ A, int lda,
         const __nv_bfloat16* __restrict__ B, int ldb,
         const float* __restrict__ bias,
         float* __restrict__ C, int ldc, int Kp, int Nact)
{
    __shared__ __align__(128) unsigned char smem_raw[3 * 16384];

    const int tid  = threadIdx.x;
    const int wid  = tid >> 5;
    const int lane = tid & 31;
    const int wm   = wid >> 2;        // 0..1
    const int wn   = wid & 3;         // 0..3
    const int rowBase = blockIdx.y * 128;
    const int colBase = blockIdx.x * 128;
    const int nch = Kp >> 5;          // K chunks of 32

    const unsigned int sbase = smem_u32(smem_raw);

    float acc[4][4][4];
    #pragma unroll
    for (int mf = 0; mf < 4; mf++)
        #pragma unroll
        for (int nf = 0; nf < 4; nf++)
            #pragma unroll
            for (int r = 0; r < 4; r++) acc[mf][nf][r] = 0.f;

    // ldmatrix per-lane row/col-16B selectors
    const int aRow = (lane & 7) + ((lane >> 3) & 1) * 8;
    const int aC16 = (lane >> 4);            // 0/1 -> k 0..7 / 8..15
    const int bRow = (lane & 7) + ((lane >> 4) & 1) * 8;
    const int bC16 = ((lane >> 3) & 1);

    const __nv_bfloat16* Atile = A + (size_t)rowBase * lda;
    const __nv_bfloat16* Btile = B + (size_t)colBase * ldb;

    // loader: thread covers 2 16B units of A and 2 of B per chunk
    const int lu0 = tid;           // 0..255
    const int lu1 = tid + 256;     // 256..511
    const int lr0 = lu0 >> 2, lc0 = lu0 & 3;
    const int lr1 = lu1 >> 2, lc1 = lu1 & 3;
    const unsigned int so0 = (unsigned int)(lr0 * 64 + ((lc0 ^ (lr0 & 3)) << 4));
    const unsigned int so1 = (unsigned int)(lr1 * 64 + ((lc1 ^ (lr1 & 3)) << 4));
    const __nv_bfloat16* Ag0 = Atile + (size_t)lr0 * lda + lc0 * 8;
    const __nv_bfloat16* Ag1 = Atile + (size_t)lr1 * lda + lc1 * 8;
    const __nv_bfloat16* Bg0 = Btile + (size_t)lr0 * ldb + lc0 * 8;
    const __nv_bfloat16* Bg1 = Btile + (size_t)lr1 * ldb + lc1 * 8;

    // prologue: stages 0,1
    {
        unsigned int st = sbase;
        CP_ASYNC16(st + so0, Ag0);
        CP_ASYNC16(st + so1, Ag1);
        CP_ASYNC16(st + 8192u + so0, Bg0);
        CP_ASYNC16(st + 8192u + so1, Bg1);
        CP_COMMIT();
        if (nch > 1) {
            st = sbase + 16384u;
            CP_ASYNC16(st + so0, Ag0 + 32);
            CP_ASYNC16(st + so1, Ag1 + 32);
            CP_ASYNC16(st + 8192u + so0, Bg0 + 32);
            CP_ASYNC16(st + 8192u + so1, Bg1 + 32);
        }
        CP_COMMIT();
    }

    int stage = 0;
    for (int c = 0; c < nch; c++) {
        CP_WAIT1();
        __syncthreads();

        // issue load for chunk c+2 into the stage freed at iteration c-1
        if (c + 2 < nch) {
            int s2 = stage + 2; if (s2 >= 3) s2 -= 3;
            unsigned int st = sbase + (unsigned int)s2 * 16384u;
            int co = (c + 2) * 32;
            CP_ASYNC16(st + so0, Ag0 + co);
            CP_ASYNC16(st + so1, Ag1 + co);
            CP_ASYNC16(st + 8192u + so0, Bg0 + co);
            CP_ASYNC16(st + 8192u + so1, Bg1 + co);
        }
        CP_COMMIT();

        const unsigned int sA = sbase + (unsigned int)stage * 16384u;
        const unsigned int sB = sA + 8192u;

        #pragma unroll
        for (int ks = 0; ks < 2; ks++) {
            unsigned int afr[4][4];
            unsigned int bfr[4][2];
            #pragma unroll
            for (int mf = 0; mf < 4; mf++) {
                int r = wm * 64 + mf * 16 + aRow;
                int c16 = ks * 2 + aC16;
                unsigned int off = (unsigned int)(r * 64 + ((c16 ^ (r & 3)) << 4));
                LDSM_X4(afr[mf][0], afr[mf][1], afr[mf][2], afr[mf][3], sA + off);
            }
            #pragma unroll
            for (int bp = 0; bp < 2; bp++) {
                int r = wn * 32 + bp * 16 + bRow;
                int c16 = ks * 2 + bC16;
                unsigned int off = (unsigned int)(r * 64 + ((c16 ^ (r & 3)) << 4));
                LDSM_X4(bfr[bp*2][0], bfr[bp*2][1],
                        bfr[bp*2+1][0], bfr[bp*2+1][1], sB + off);
            }
            #pragma unroll
            for (int mf = 0; mf < 4; mf++)
                #pragma unroll
                for (int nf = 0; nf < 4; nf++)
                    MMA16816(acc[mf][nf], afr[mf], bfr[nf]);
        }

        stage++; if (stage >= 3) stage -= 3;
    }

    // ---- epilogue ----
    #pragma unroll
    for (int mf = 0; mf < 4; mf++) {
        int r0 = rowBase + wm * 64 + mf * 16 + (lane >> 2);
        #pragma unroll
        for (int nf = 0; nf < 4; nf++) {
            int c0 = colBase + wn * 32 + nf * 8 + (lane & 3) * 2;
            if (c0 < Nact) {
                float v0 = acc[mf][nf][0];
                float v1 = acc[mf][nf][1];
                float v2 = acc[mf][nf][2];
                float v3 = acc[mf][nf][3];
                if (EPI >= 1) {
                    float b0 = bias[c0];
                    float b1 = bias[c0 + 1];
                    v0 += b0; v1 += b1; v2 += b0; v3 += b1;
                }
                if (EPI == 2) {
                    v0 = fmaxf(v0, 0.f) + log1pf(expf(-fabsf(v0)));
                    v1 = fmaxf(v1, 0.f) + log1pf(expf(-fabsf(v1)));
                    v2 = fmaxf(v2, 0.f) + log1pf(expf(-fabsf(v2)));
                    v3 = fmaxf(v3, 0.f) + log1pf(expf(-fabsf(v3)));
                }
                size_t o0 = (size_t)r0 * ldc + c0;
                size_t o1 = (size_t)(r0 + 8) * ldc + c0;
                if (EPI == 3) {
                    v0 += C[o0]; v1 += C[o0 + 1];
                    v2 += C[o1]; v3 += C[o1 + 1];
                }
                C[o0] = v0; C[o0 + 1] = v1;
                C[o1] = v2; C[o1 + 1] = v3;
            }
        }
    }
}

// ======================= split conversion =================================
__device__ __forceinline__ void split2(float v, __nv_bfloat16& hi, __nv_bfloat16& lo) {
    hi = __float2bfloat16(v);
    lo = __float2bfloat16(v - __bfloat162float(hi));
}

// weights: B' = [hi | hi | lo]
__global__ void __launch_bounds__(256)
wsplit(const float* __restrict__ W, __nv_bfloat16* __restrict__ out, int N, int K)
{
    int i = blockIdx.x * 256 + threadIdx.x;
    if (i >= N * K) return;
    int n = i / K;
    int k = i - n * K;
    __nv_bfloat16 hi, lo;
    split2(W[i], hi, lo);
    size_t b = (size_t)n * 3 * K;
    out[b + k] = hi;
    out[b + K + k] = hi;
    out[b + 2 * K + k] = lo;
}

// dbc cols [0,64) -> A' split [SEQ,192]
__global__ void __launch_bounds__(256)
split_dbc(const float* __restrict__ dbc, __nv_bfloat16* __restrict__ out)
{
    int i = blockIdx.x * 256 + threadIdx.x;
    if (i >= SEQ * 64) return;
    int row = i >> 6;
    int col = i & 63;
    __nv_bfloat16 hi, lo;
    split2(dbc[row * 96 + col], hi, lo);
    size_t b = (size_t)row * 192;
    out[b + col] = hi;
    out[b + 64 + col] = lo;
    out[b + 128 + col] = hi;
}

// ---------------- block reduce (sum, sumsq) --------------------------------
__device__ __forceinline__ float2 block_reduce2(float sx, float sq) {
    __shared__ float shx[8];
    __shared__ float shq[8];
    const unsigned m = 0xffffffffu;
    #pragma unroll
    for (int o = 16; o > 0; o >>= 1) {
        sx += __shfl_xor_sync(m, sx, o);
        sq += __shfl_xor_sync(m, sq, o);
    }
    int w = threadIdx.x >> 5;
    if ((threadIdx.x & 31) == 0) { shx[w] = sx; shq[w] = sq; }
    __syncthreads();
    if (threadIdx.x == 0) {
        float ax = 0.f;
        float aq = 0.f;
        #pragma unroll
        for (int i = 0; i < 8; i++) { ax += shx[i]; aq += shq[i]; }
        shx[0] = ax;
        shq[0] = aq;
    }
    __syncthreads();
    return make_float2(shx[0], shq[0]);
}

// ---------------- layernorm family -----------------------------------------
// MODE 0: LN(x); MODE 1: LN(x+x2); MODE 2: LN(x)*silu(x2[row*ld2+off2+i])
// SPLITK==0: write fp32 to outf; SPLITK>0: write bf16 split [hi|lo|hi] to outs
template<int VPT, int MODE, int SPLITK>
__global__ void __launch_bounds__(256)
ln_kernel(const float* __restrict__ x, const float* __restrict__ x2,
          int ld2, int off2,
          const float* __restrict__ g, const float* __restrict__ b,
          float* __restrict__ outf, __nv_bfloat16* __restrict__ outs,
          int D, float eps)
{
    const int row = blockIdx.x;
    float v[VPT];
    float sx = 0.f;
    float sq = 0.f;
    #pragma unroll
    for (int i = 0; i < VPT; i++) {
        int idx = threadIdx.x + i * 256;
        float t = x[(size_t)row * D + idx];
        if (MODE == 1) t += x2[(size_t)row * D + idx];
        v[i] = t;
        sx += t;
        sq += t * t;
    }
    float2 s = block_reduce2(sx, sq);
    float mu = s.x / (float)D;
    float var = s.y / (float)D - mu * mu;
    float rs = rsqrtf(var + eps);
    #pragma unroll
    for (int i = 0; i < VPT; i++) {
        int idx = threadIdx.x + i * 256;
        float o = (v[i] - mu) * rs * g[idx] + b[idx];
        if (MODE == 2) {
            float z = x2[(size_t)row * ld2 + off2 + idx];
            o *= z / (1.f + __expf(-z));
        }
        if (SPLITK == 0) {
            outf[(size_t)row * D + idx] = o;
        } else {
            __nv_bfloat16 hi, lo;
            split2(o, hi, lo);
            size_t rb = (size_t)row * 3 * SPLITK;
            outs[rb + idx] = hi;
            outs[rb + SPLITK + idx] = lo;
            outs[rb + 2 * SPLITK + idx] = hi;
        }
    }
}

// ---------------- depthwise conv1d k=3, pad=1 (+ bf16 split of u) ----------
__global__ void __launch_bounds__(256)
conv_kernel(const float* __restrict__ xz, const float* __restrict__ w,
            const float* __restrict__ b, float* __restrict__ u,
            __nv_bfloat16* __restrict__ usplit)
{
    int idx = blockIdx.x * 256 + threadIdx.x;     // < SEQ*DI
    int d = idx & (DI - 1);
    int t = idx >> 11;
    float w0 = w[d*3+0];
    float w1 = w[d*3+1];
    float w2 = w[d*3+2];
    const float* col = xz + d;
    float xm = (t > 0)       ? col[(size_t)(t-1) * (2*DI)] : 0.f;
    float x0 =                 col[(size_t)t     * (2*DI)];
    float xp = (t < SEQ - 1) ? col[(size_t)(t+1) * (2*DI)] : 0.f;
    float v = fmaf(w0, xm, fmaf(w1, x0, fmaf(w2, xp, b[d])));
    u[idx] = v;
    __nv_bfloat16 hi, lo;
    split2(v, hi, lo);
    size_t rb = (size_t)t * 3 * DI;
    usplit[rb + d] = hi;
    usplit[rb + DI + d] = lo;
    usplit[rb + 2 * DI + d] = hi;
}

// ---------------- scan helpers ---------------------------------------------
__device__ __forceinline__ void load_A_fast(const float* __restrict__ A_log, int d,
                                            float* a, bool& fast, float& a0)
{
    #pragma unroll
    for (int n = 0; n < NST; n++) a[n] = -__expf(A_log[(size_t)d * NST + n]);
    a0 = a[0];
    fast = true;
    #pragma unroll
    for (int n = 1; n < NST; n++)
        fast = fast && (fabsf(a[n] - (float)(n+1) * a0) <= 2e-5f * (float)(n+1));
}

__global__ void __launch_bounds__(256)
scan_pass_a(const float* __restrict__ delta, const float* __restrict__ u,
            const float* __restrict__ dbc, const float* __restrict__ A_log,
            float* __restrict__ hl, float* __restrict__ pp)
{
    __shared__ float Bsh[CHUNK][NST];
    const int d = blockIdx.x * 256 + threadIdx.x;
    const int c = blockIdx.y;
    for (int i = threadIdx.x; i < CHUNK * NST; i += 256) {
        int t = i >> 4;
        int n = i & 15;
        Bsh[t][n] = dbc[(size_t)(c*CHUNK + t) * 96 + 64 + n];
    }
    __syncthreads();

    float a[NST];
    bool fast;
    float a0;
    load_A_fast(A_log, d, a, fast, a0);

    float h[NST];
    float p[NST];
    #pragma unroll
    for (int n = 0; n < NST; n++) { h[n] = 0.f; p[n] = 1.f; }

    const int t0 = c * CHUNK;
    for (int t = 0; t < CHUNK; t++) {
        float dlt = delta[(size_t)(t0 + t) * DI + d];
        float uu  = u[(size_t)(t0 + t) * DI + d];
        float du  = dlt * uu;
        float dAv[NST];
        if (fast) {
            float e = __expf(dlt * a0);
            float w = e;
            #pragma unroll
            for (int n = 0; n < NST; n++) { dAv[n] = w; w *= e; }
        } else {
            #pragma unroll
            for (int n = 0; n < NST; n++) dAv[n] = __expf(dlt * a[n]);
        }
        #pragma unroll
        for (int n = 0; n < NST; n++) {
            h[n] = fmaf(dAv[n], h[n], du * Bsh[t][n]);
            p[n] *= dAv[n];
        }
    }
    #pragma unroll
    for (int n = 0; n < NST; n++) {
        size_t o = ((size_t)c * NST + n) * DI + d;
        hl[o] = h[n];
        pp[o] = p[n];
    }
}

__global__ void __launch_bounds__(256)
scan_pass_b(const float* __restrict__ hl, const float* __restrict__ pp,
            float* __restrict__ h0)
{
    int i = blockIdx.x * 256 + threadIdx.x;
    if (i >= NST * DI) return;
    float h = 0.f;
    for (int c = 0; c < NCH; c++) {
        size_t idx = (size_t)c * NST * DI + i;
        h0[idx] = h;
        h = fmaf(pp[idx], h, hl[idx]);
    }
}

__global__ void __launch_bounds__(256)
scan_pass_c(const float* __restrict__ delta, const float* __restrict__ u,
            const float* __restrict__ dbc, const float* __restrict__ A_log,
            const float* __restrict__ Dp, const float* __restrict__ h0,
            float* __restrict__ y)
{
    __shared__ float Bsh[CHUNK][NST];
    __shared__ float Csh[CHUNK][NST];
    const int d = blockIdx.x * 256 + threadIdx.x;
    const int c = blockIdx.y;
    for (int i = threadIdx.x; i < CHUNK * NST; i += 256) {
        int t = i >> 4;
        int n = i & 15;
        Bsh[t][n] = dbc[(size_t)(c*CHUNK + t) * 96 + 64 + n];
        Csh[t][n] = dbc[(size_t)(c*CHUNK + t) * 96 + 80 + n];
    }
    __syncthreads();

    float a[NST];
    bool fast;
    float a0;
    load_A_fast(A_log, d, a, fast, a0);
    float Dv = Dp[d];

    float h[NST];
    #pragma unroll
    for (int n = 0; n < NST; n++) h[n] = h0[((size_t)c * NST + n) * DI + d];

    const int t0 = c * CHUNK;
    for (int t = 0; t < CHUNK; t++) {
        float dlt = delta[(size_t)(t0 + t) * DI + d];
        float uu  = u[(size_t)(t0 + t) * DI + d];
        float du  = dlt * uu;
        float dAv[NST];
        if (fast) {
            float e = __expf(dlt * a0);
            float w = e;
            #pragma unroll
            for (int n = 0; n < NST; n++) { dAv[n] = w; w *= e; }
        } else {
            #pragma unroll
            for (int n = 0; n < NST; n++) dAv[n] = __expf(dlt * a[n]);
        }
        float yv = 0.f;
        #pragma unroll
        for (int n = 0; n < NST; n++) {
            h[n] = fmaf(dAv[n], h[n], du * Bsh[t][n]);
            yv = fmaf(h[n], Csh[t][n], yv);
        }
        y[(size_t)(t0 + t) * DI + d] = fmaf(Dv, uu, yv);
    }
}

// ---------------- host ------------------------------------------------------
extern "C" void kernel_launch(void* const* d_in, const int* in_sizes, int n_in,
                              void* d_out, int out_size)
{
    const float* x         = (const float*)d_in[0];
    const float* pos_enc   = (const float*)d_in[1];
    const float* ln_g      = (const float*)d_in[2];
    const float* ln_b      = (const float*)d_in[3];
    const float* innorm_g  = (const float*)d_in[4];
    const float* innorm_b  = (const float*)d_in[5];
    const float* in_proj_w = (const float*)d_in[6];
    const float* in_proj_b = (const float*)d_in[7];
    const float* conv_w    = (const float*)d_in[8];
    const float* conv_b    = (const float*)d_in[9];
    const float* deltaBC_w = (const float*)d_in[10];
    const float* dt_proj_w = (const float*)d_in[11];
    const float* dt_proj_b = (const float*)d_in[12];
    const float* A_log     = (const float*)d_in[13];
    const float* Dp        = (const float*)d_in[14];
    const float* outnorm_g = (const float*)d_in[15];
    const float* outnorm_b = (const float*)d_in[16];
    const float* out_proj_w= (const float*)d_in[17];
    const float* out_proj_b= (const float*)d_in[18];

    float* enc = 0;
    float* xz = 0;
    float* u = 0;
    float* dbc = 0;
    float* delta = 0;
    float* y = 0;
    float* hl = 0;
    float* pp = 0;
    float* h0 = 0;
    __nv_bfloat16* hbufs = 0;
    __nv_bfloat16* usplit = 0;
    __nv_bfloat16* dbcs = 0;
    __nv_bfloat16* y2s = 0;
    __nv_bfloat16* win = 0;
    __nv_bfloat16* wdbc = 0;
    __nv_bfloat16* wdt = 0;
    __nv_bfloat16* wout = 0;
    cudaGetSymbolAddress((void**)&enc,   g_enc);
    cudaGetSymbolAddress((void**)&xz,    g_xz);
    cudaGetSymbolAddress((void**)&u,     g_u);
    cudaGetSymbolAddress((void**)&dbc,   g_dbc);
    cudaGetSymbolAddress((void**)&delta, g_delta);
    cudaGetSymbolAddress((void**)&y,     g_y);
    cudaGetSymbolAddress((void**)&hl,    g_hl);
    cudaGetSymbolAddress((void**)&pp,    g_pp);
    cudaGetSymbolAddress((void**)&h0,    g_h0);
    cudaGetSymbolAddress((void**)&hbufs, g_hbufs);
    cudaGetSymbolAddress((void**)&usplit,g_us);
    cudaGetSymbolAddress((void**)&dbcs,  g_dbcs);
    cudaGetSymbolAddress((void**)&y2s,   g_y2s);
    cudaGetSymbolAddress((void**)&win,   g_win);
    cudaGetSymbolAddress((void**)&wdbc,  g_wdbc);
    cudaGetSymbolAddress((void**)&wdt,   g_wdt);
    cudaGetSymbolAddress((void**)&wout,  g_wout);

    // weight splits (recomputed every call — determinism)
    {
        int n1 = NL * 2*DI * DM;
        wsplit<<<(n1+255)/256, 256>>>(in_proj_w, win, NL*2*DI, DM);
        int n2 = NL * DM * DI;
        wsplit<<<(n2+255)/256, 256>>>(out_proj_w, wout, NL*DM, DI);
        int n3 = NL * DI * 64;
        wsplit<<<(n3+255)/256, 256>>>(dt_proj_w, wdt, NL*DI, 64);
        for (int l = 0; l < NL; l++) {
            int n4 = 96 * DI;
            wsplit<<<(n4+255)/256, 256>>>(deltaBC_w + (size_t)l*96*DI,
                                          wdbc + (size_t)l*128*3*DI, 96, DI);
        }
    }

    // pre-encoder: enc = LN(x + pos_enc), eps=1e-6
    ln_kernel<4,1,0><<<SEQ, 256>>>(x, pos_enc, DM, 0, ln_g, ln_b, enc, (__nv_bfloat16*)0, DM, 1e-6f);

    for (int l = 0; l < NL; l++) {
        // 1) hbufs = split(LN(enc))
        ln_kernel<4,0,DM><<<SEQ, 256>>>(enc, (const float*)0, 0, 0,
                                        innorm_g + (size_t)l*DM, innorm_b + (size_t)l*DM,
                                        (float*)0, hbufs, DM, 1e-5f);
        // 2) xz = hbuf @ in_proj_w^T + b  (M=4096 N=4096 K'=3072)
        gemm_mma<1><<<dim3(2*DI/128, SEQ/128), 256>>>(
            hbufs, 3*DM, win + (size_t)l*2*DI*3*DM, 3*DM,
            in_proj_b + (size_t)l*2*DI, xz, 2*DI, 3*DM, 2*DI);
        // 3) depthwise conv -> u (+split)
        conv_kernel<<<SEQ*DI/256, 256>>>(xz, conv_w + (size_t)l*DI*3,
                                         conv_b + (size_t)l*DI, u, usplit);
        // 4) dbc = u @ deltaBC_w^T (N=96 padded to 128 tile, K'=6144)
        gemm_mma<0><<<dim3(1, SEQ/128), 256>>>(
            usplit, 3*DI, wdbc + (size_t)l*128*3*DI, 3*DI,
            (const float*)0, dbc, 96, 3*DI, 96);
        split_dbc<<<SEQ*64/256, 256>>>(dbc, dbcs);
        // 5) delta = softplus(dbc[:,:64] @ dt_proj_w^T + b)  (K'=192)
        gemm_mma<2><<<dim3(DI/128, SEQ/128), 256>>>(
            dbcs, 192, wdt + (size_t)l*DI*192, 192,
            dt_proj_b + (size_t)l*DI, delta, DI, 192, DI);
        // 6) chunked selective scan
        scan_pass_a<<<dim3(DI/256, NCH), 256>>>(delta, u, dbc,
                                                A_log + (size_t)l*DI*NST, hl, pp);
        scan_pass_b<<<(NST*DI)/256, 256>>>(hl, pp, h0);
        scan_pass_c<<<dim3(DI/256, NCH), 256>>>(delta, u, dbc,
                                                A_log + (size_t)l*DI*NST,
                                                Dp + (size_t)l*DI, h0, y);
        // 7) y2s = split(LN(y) * silu(z))
        ln_kernel<8,2,DI><<<SEQ, 256>>>(y, xz, 2*DI, DI,
                                        outnorm_g + (size_t)l*DI, outnorm_b + (size_t)l*DI,
                                        (float*)0, y2s, DI, 1e-5f);
        // 8) enc = y2 @ out_proj_w^T + b + enc  (K'=6144)
        gemm_mma<3><<<dim3(DM/128, SEQ/128), 256>>>(
            y2s, 3*DI, wout + (size_t)l*DM*3*DI, 3*DI,
            out_proj_b + (size_t)l*DM, enc, DM, 3*DI, DM);
    }

    cudaMemcpyAsync(d_out, enc, sizeof(float) * (size_t)out_size,
                    cudaMemcpyDeviceToDevice);
}

// round 13
// speedup vs baseline: 1.8608x; 1.1913x over previous
#include <cuda_runtime.h>
#include <cuda_bf16.h>
#include <cstdint>
#include <math.h>

#define SEQ   4096
#define DM    1024
#define DI    2048
#define NST   16
#define NL    4
#define NCH   64
#define CHUNK 64
#define KSP   4          // split-K factor for deltaBC GEMM

// ---------------- scratch (device globals; no allocation allowed) ----------
__device__ float g_enc[SEQ*DM];
__device__ float g_xz[SEQ*2*DI];
__device__ float g_u[SEQ*DI];
__device__ float g_dbc[SEQ*96];
__device__ float g_dbcp[KSP*SEQ*96];
__device__ float g_delta[SEQ*DI];
__device__ float g_y[SEQ*DI];
__device__ float g_hl[NCH*NST*DI];
__device__ float g_pp[NCH*NST*DI];
__device__ float g_h0[NCH*NST*DI];
// bf16 split activations (A' = [hi | lo | hi] along K)
__device__ __nv_bfloat16 g_hbufs[SEQ*3*DM];
__device__ __nv_bfloat16 g_us[SEQ*3*DI];
__device__ __nv_bfloat16 g_dbcs[SEQ*3*64];
__device__ __nv_bfloat16 g_y2s[SEQ*3*DI];
// bf16 split weights (B' = [hi | hi | lo] along K)
__device__ __nv_bfloat16 g_win[NL*(2*DI)*(3*DM)];
__device__ __nv_bfloat16 g_wdbc[NL*128*(3*DI)];   // padded 96->128 rows (pad stays 0)
__device__ __nv_bfloat16 g_wdt[NL*DI*(3*64)];
__device__ __nv_bfloat16 g_wout[NL*DM*(3*DI)];

// ======================= helpers ============================================
__device__ __forceinline__ unsigned int smem_u32(const void* smem_ptr) {
    unsigned int addr;
    asm("{ .reg .u64 tmp; cvta.to.shared.u64 tmp, %1; cvt.u32.u64 %0, tmp; }"
        : "=r"(addr) : "l"(smem_ptr));
    return addr;
}

#define LDSM_X4(r0, r1, r2, r3, addr) \
    asm volatile( \
        "ldmatrix.sync.aligned.m8n8.x4.shared.b16 {%0, %1, %2, %3}, [%4];" \
        : "=r"(r0), "=r"(r1), "=r"(r2), "=r"(r3) : "r"(addr))

#define MMA16816(c, a, b) \
    asm volatile( \
        "mma.sync.aligned.m16n8k16.row.col.f32.bf16.bf16.f32 " \
        "{%0, %1, %2, %3}, {%4, %5, %6, %7}, {%8, %9}, {%0, %1, %2, %3};" \
        : "+f"((c)[0]), "+f"((c)[1]), "+f"((c)[2]), "+f"((c)[3]) \
        : "r"((a)[0]), "r"((a)[1]), "r"((a)[2]), "r"((a)[3]), \
          "r"((b)[0]), "r"((b)[1]))

#define CP_ASYNC16(dst, src) \
    asm volatile("cp.async.cg.shared.global [%0], [%1], 16;" \
                 :: "r"(dst), "l"(src) : "memory")
#define CP_COMMIT() \
    asm volatile("cp.async.commit_group;" ::: "memory")
#define CP_WAIT1() \
    asm volatile("cp.async.wait_group 1;" ::: "memory")

// ======================= bf16 mma.sync GEMM (NT), cp.async pipelined ========
// C[m,n] = sum_k A'[m,k] * B'[n,k].  A': [M,*] bf16 lda, B': [Npad,*] bf16 ldb.
// Kspan % 32 == 0. 128x128 CTA tile, 128 threads (4 warps = 2m x 2n, warp
// tile 64x64). K chunks of 32; 3 smem stages (16KB each, 48KB static).
// smem rows 64B; swizzle: 16B-unit col ^= (row & 3).
// blockIdx.z (split-K): k offset = z*Kspan, C += z*sliceStride.
// EPI: 0 store (masked to Nact), 1 +bias, 2 +bias->softplus, 3 +bias +C
template<int EPI>
__global__ void __launch_bounds__(128)
gemm_mma(const __nv_bfloat16* __restrict__ A, int lda,
         const __nv_bfloat16* __restrict__ B, int ldb,
         const float* __restrict__ bias,
         float* __restrict__ C, int ldc, int Kspan, int Nact,
         long long sliceStride)
{
    __shared__ __align__(128) unsigned char smem_raw[3 * 16384];

    const int tid  = threadIdx.x;
    const int wid  = tid >> 5;
    const int lane = tid & 31;
    const int wm   = wid >> 1;        // 0..1
    const int wn   = wid & 1;         // 0..1
    const int rowBase = blockIdx.y * 128;
    const int colBase = blockIdx.x * 128;
    const int kOff = blockIdx.z * Kspan;
    const int nch = Kspan >> 5;       // K chunks of 32
    C += (long long)blockIdx.z * sliceStride;

    const unsigned int sbase = smem_u32(smem_raw);

    float acc[4][8][4];
    #pragma unroll
    for (int mf = 0; mf < 4; mf++)
        #pragma unroll
        for (int nf = 0; nf < 8; nf++)
            #pragma unroll
            for (int r = 0; r < 4; r++) acc[mf][nf][r] = 0.f;

    // ldmatrix per-lane row/col-16B selectors
    const int aRow = (lane & 7) + ((lane >> 3) & 1) * 8;
    const int aC16 = (lane >> 4);            // 0/1 -> k 0..7 / 8..15
    const int bRow = (lane & 7) + ((lane >> 4) & 1) * 8;
    const int bC16 = ((lane >> 3) & 1);

    const __nv_bfloat16* Atile = A + (size_t)rowBase * lda + kOff;
    const __nv_bfloat16* Btile = B + (size_t)colBase * ldb + kOff;

    // loader: 1024 16B units per chunk (A 0..511, B 512..1023); 8 per thread
    unsigned int so[8];
    const __nv_bfloat16* gp[8];
    #pragma unroll
    for (int j = 0; j < 8; j++) {
        int unit = tid + j * 128;                 // 0..1023
        int isB = (unit >= 512);
        int u = unit & 511;
        int r = u >> 2;
        int cc = u & 3;
        so[j] = (unsigned int)(isB * 8192 + r * 64 + ((cc ^ (r & 3)) << 4));
        const __nv_bfloat16* base = isB ? Btile : Atile;
        int ld = isB ? ldb : lda;
        gp[j] = base + (size_t)r * ld + cc * 8;
    }

    // prologue: stages 0,1
    {
        #pragma unroll
        for (int j = 0; j < 8; j++) CP_ASYNC16(sbase + so[j], gp[j]);
        CP_COMMIT();
        if (nch > 1) {
            #pragma unroll
            for (int j = 0; j < 8; j++)
                CP_ASYNC16(sbase + 16384u + so[j], gp[j] + 32);
        }
        CP_COMMIT();
    }

    int stage = 0;
    for (int c = 0; c < nch; c++) {
        CP_WAIT1();
        __syncthreads();

        // issue load for chunk c+2 into the stage freed at iteration c-1
        if (c + 2 < nch) {
            int s2 = stage + 2; if (s2 >= 3) s2 -= 3;
            unsigned int st = sbase + (unsigned int)s2 * 16384u;
            int co = (c + 2) * 32;
            #pragma unroll
            for (int j = 0; j < 8; j++) CP_ASYNC16(st + so[j], gp[j] + co);
        }
        CP_COMMIT();

        const unsigned int sA = sbase + (unsigned int)stage * 16384u;
        const unsigned int sB = sA + 8192u;

        #pragma unroll
        for (int ks = 0; ks < 2; ks++) {
            unsigned int afr[4][4];
            unsigned int bfr[8][2];
            #pragma unroll
            for (int mf = 0; mf < 4; mf++) {
                int r = wm * 64 + mf * 16 + aRow;
                int c16 = ks * 2 + aC16;
                unsigned int off = (unsigned int)(r * 64 + ((c16 ^ (r & 3)) << 4));
                LDSM_X4(afr[mf][0], afr[mf][1], afr[mf][2], afr[mf][3], sA + off);
            }
            #pragma unroll
            for (int bp = 0; bp < 4; bp++) {
                int r = wn * 64 + bp * 16 + bRow;
                int c16 = ks * 2 + bC16;
                unsigned int off = (unsigned int)(r * 64 + ((c16 ^ (r & 3)) << 4));
                LDSM_X4(bfr[bp*2][0], bfr[bp*2][1],
                        bfr[bp*2+1][0], bfr[bp*2+1][1], sB + off);
            }
            #pragma unroll
            for (int mf = 0; mf < 4; mf++)
                #pragma unroll
                for (int nf = 0; nf < 8; nf++)
                    MMA16816(acc[mf][nf], afr[mf], bfr[nf]);
        }

        stage++; if (stage >= 3) stage -= 3;
    }

    // ---- epilogue ----
    #pragma unroll
    for (int mf = 0; mf < 4; mf++) {
        int r0 = rowBase + wm * 64 + mf * 16 + (lane >> 2);
        #pragma unroll
        for (int nf = 0; nf < 8; nf++) {
            int c0 = colBase + wn * 64 + nf * 8 + (lane & 3) * 2;
            if (c0 < Nact) {
                float v0 = acc[mf][nf][0];
                float v1 = acc[mf][nf][1];
                float v2 = acc[mf][nf][2];
                float v3 = acc[mf][nf][3];
                if (EPI >= 1) {
                    float b0 = bias[c0];
                    float b1 = bias[c0 + 1];
                    v0 += b0; v1 += b1; v2 += b0; v3 += b1;
                }
                if (EPI == 2) {
                    v0 = fmaxf(v0, 0.f) + log1pf(expf(-fabsf(v0)));
                    v1 = fmaxf(v1, 0.f) + log1pf(expf(-fabsf(v1)));
                    v2 = fmaxf(v2, 0.f) + log1pf(expf(-fabsf(v2)));
                    v3 = fmaxf(v3, 0.f) + log1pf(expf(-fabsf(v3)));
                }
                size_t o0 = (size_t)r0 * ldc + c0;
                size_t o1 = (size_t)(r0 + 8) * ldc + c0;
                if (EPI == 3) {
                    v0 += C[o0]; v1 += C[o0 + 1];
                    v2 += C[o1]; v3 += C[o1 + 1];
                }
                C[o0] = v0; C[o0 + 1] = v1;
                C[o1] = v2; C[o1 + 1] = v3;
            }
        }
    }
}

// ---------------- split-K reduce (deterministic) ----------------------------
__global__ void __launch_bounds__(256)
reduce_ks(const float* __restrict__ part, float* __restrict__ out, int n)
{
    int i = blockIdx.x * 256 + threadIdx.x;
    if (i < n) {
        float s = 0.f;
        #pragma unroll
        for (int z = 0; z < KSP; z++) s += part[(size_t)z * n + i];
        out[i] = s;
    }
}

// ======================= split conversion =================================
__device__ __forceinline__ void split2(float v, __nv_bfloat16& hi, __nv_bfloat16& lo) {
    hi = __float2bfloat16(v);
    lo = __float2bfloat16(v - __bfloat162float(hi));
}

// weights: B' = [hi | hi | lo]
__global__ void __launch_bounds__(256)
wsplit(const float* __restrict__ W, __nv_bfloat16* __restrict__ out, int N, int K)
{
    int i = blockIdx.x * 256 + threadIdx.x;
    if (i >= N * K) return;
    int n = i / K;
    int k = i - n * K;
    __nv_bfloat16 hi, lo;
    split2(W[i], hi, lo);
    size_t b = (size_t)n * 3 * K;
    out[b + k] = hi;
    out[b + K + k] = hi;
    out[b + 2 * K + k] = lo;
}

// dbc cols [0,64) -> A' split [SEQ,192]
__global__ void __launch_bounds__(256)
split_dbc(const float* __restrict__ dbc, __nv_bfloat16* __restrict__ out)
{
    int i = blockIdx.x * 256 + threadIdx.x;
    if (i >= SEQ * 64) return;
    int row = i >> 6;
    int col = i & 63;
    __nv_bfloat16 hi, lo;
    split2(dbc[row * 96 + col], hi, lo);
    size_t b = (size_t)row * 192;
    out[b + col] = hi;
    out[b + 64 + col] = lo;
    out[b + 128 + col] = hi;
}

// ---------------- block reduce (sum, sumsq) --------------------------------
__device__ __forceinline__ float2 block_reduce2(float sx, float sq) {
    __shared__ float shx[8];
    __shared__ float shq[8];
    const unsigned m = 0xffffffffu;
    #pragma unroll
    for (int o = 16; o > 0; o >>= 1) {
        sx += __shfl_xor_sync(m, sx, o);
        sq += __shfl_xor_sync(m, sq, o);
    }
    int w = threadIdx.x >> 5;
    if ((threadIdx.x & 31) == 0) { shx[w] = sx; shq[w] = sq; }
    __syncthreads();
    if (threadIdx.x == 0) {
        float ax = 0.f;
        float aq = 0.f;
        #pragma unroll
        for (int i = 0; i < 8; i++) { ax += shx[i]; aq += shq[i]; }
        shx[0] = ax;
        shq[0] = aq;
    }
    __syncthreads();
    return make_float2(shx[0], shq[0]);
}

// ---------------- layernorm family -----------------------------------------
// MODE 0: LN(x); MODE 1: LN(x+x2); MODE 2: LN(x)*silu(x2[row*ld2+off2+i])
// SPLITK==0: write fp32 to outf; SPLITK>0: write bf16 split [hi|lo|hi] to outs
template<int VPT, int MODE, int SPLITK>
__global__ void __launch_bounds__(256)
ln_kernel(const float* __restrict__ x, const float* __restrict__ x2,
          int ld2, int off2,
          const float* __restrict__ g, const float* __restrict__ b,
          float* __restrict__ outf, __nv_bfloat16* __restrict__ outs,
          int D, float eps)
{
    const int row = blockIdx.x;
    float v[VPT];
    float sx = 0.f;
    float sq = 0.f;
    #pragma unroll
    for (int i = 0; i < VPT; i++) {
        int idx = threadIdx.x + i * 256;
        float t = x[(size_t)row * D + idx];
        if (MODE == 1) t += x2[(size_t)row * D + idx];
        v[i] = t;
        sx += t;
        sq += t * t;
    }
    float2 s = block_reduce2(sx, sq);
    float mu = s.x / (float)D;
    float var = s.y / (float)D - mu * mu;
    float rs = rsqrtf(var + eps);
    #pragma unroll
    for (int i = 0; i < VPT; i++) {
        int idx = threadIdx.x + i * 256;
        float o = (v[i] - mu) * rs * g[idx] + b[idx];
        if (MODE == 2) {
            float z = x2[(size_t)row * ld2 + off2 + idx];
            o *= z / (1.f + __expf(-z));
        }
        if (SPLITK == 0) {
            outf[(size_t)row * D + idx] = o;
        } else {
            __nv_bfloat16 hi, lo;
            split2(o, hi, lo);
            size_t rb = (size_t)row * 3 * SPLITK;
            outs[rb + idx] = hi;
            outs[rb + SPLITK + idx] = lo;
            outs[rb + 2 * SPLITK + idx] = hi;
        }
    }
}

// ---------------- depthwise conv1d k=3, pad=1 (+ bf16 split of u) ----------
__global__ void __launch_bounds__(256)
conv_kernel(const float* __restrict__ xz, const float* __restrict__ w,
            const float* __restrict__ b, float* __restrict__ u,
            __nv_bfloat16* __restrict__ usplit)
{
    int idx = blockIdx.x * 256 + threadIdx.x;     // < SEQ*DI
    int d = idx & (DI - 1);
    int t = idx >> 11;
    float w0 = w[d*3+0];
    float w1 = w[d*3+1];
    float w2 = w[d*3+2];
    const float* col = xz + d;
    float xm = (t > 0)       ? col[(size_t)(t-1) * (2*DI)] : 0.f;
    float x0 =                 col[(size_t)t     * (2*DI)];
    float xp = (t < SEQ - 1) ? col[(size_t)(t+1) * (2*DI)] : 0.f;
    float v = fmaf(w0, xm, fmaf(w1, x0, fmaf(w2, xp, b[d])));
    u[idx] = v;
    __nv_bfloat16 hi, lo;
    split2(v, hi, lo);
    size_t rb = (size_t)t * 3 * DI;
    usplit[rb + d] = hi;
    usplit[rb + DI + d] = lo;
    usplit[rb + 2 * DI + d] = hi;
}

// ---------------- scan helpers ---------------------------------------------
__device__ __forceinline__ void load_A_fast(const float* __restrict__ A_log, int d,
                                            float* a, bool& fast, float& a0)
{
    #pragma unroll
    for (int n = 0; n < NST; n++) a[n] = -__expf(A_log[(size_t)d * NST + n]);
    a0 = a[0];
    fast = true;
    #pragma unroll
    for (int n = 1; n < NST; n++)
        fast = fast && (fabsf(a[n] - (float)(n+1) * a0) <= 2e-5f * (float)(n+1));
}

__global__ void __launch_bounds__(256)
scan_pass_a(const float* __restrict__ delta, const float* __restrict__ u,
            const float* __restrict__ dbc, const float* __restrict__ A_log,
            float* __restrict__ hl, float* __restrict__ pp)
{
    __shared__ float Bsh[CHUNK][NST];
    const int d = blockIdx.x * 256 + threadIdx.x;
    const int c = blockIdx.y;
    for (int i = threadIdx.x; i < CHUNK * NST; i += 256) {
        int t = i >> 4;
        int n = i & 15;
        Bsh[t][n] = dbc[(size_t)(c*CHUNK + t) * 96 + 64 + n];
    }
    __syncthreads();

    float a[NST];
    bool fast;
    float a0;
    load_A_fast(A_log, d, a, fast, a0);

    float h[NST];
    float p[NST];
    #pragma unroll
    for (int n = 0; n < NST; n++) { h[n] = 0.f; p[n] = 1.f; }

    const int t0 = c * CHUNK;
    for (int t = 0; t < CHUNK; t++) {
        float dlt = delta[(size_t)(t0 + t) * DI + d];
        float uu  = u[(size_t)(t0 + t) * DI + d];
        float du  = dlt * uu;
        float dAv[NST];
        if (fast) {
            float e = __expf(dlt * a0);
            float w = e;
            #pragma unroll
            for (int n = 0; n < NST; n++) { dAv[n] = w; w *= e; }
        } else {
            #pragma unroll
            for (int n = 0; n < NST; n++) dAv[n] = __expf(dlt * a[n]);
        }
        #pragma unroll
        for (int n = 0; n < NST; n++) {
            h[n] = fmaf(dAv[n], h[n], du * Bsh[t][n]);
            p[n] *= dAv[n];
        }
    }
    #pragma unroll
    for (int n = 0; n < NST; n++) {
        size_t o = ((size_t)c * NST + n) * DI + d;
        hl[o] = h[n];
        pp[o] = p[n];
    }
}

__global__ void __launch_bounds__(256)
scan_pass_b(const float* __restrict__ hl, const float* __restrict__ pp,
            float* __restrict__ h0)
{
    int i = blockIdx.x * 256 + threadIdx.x;
    if (i >= NST * DI) return;
    float h = 0.f;
    for (int c = 0; c < NCH; c++) {
        size_t idx = (size_t)c * NST * DI + i;
        h0[idx] = h;
        h = fmaf(pp[idx], h, hl[idx]);
    }
}

__global__ void __launch_bounds__(256)
scan_pass_c(const float* __restrict__ delta, const float* __restrict__ u,
            const float* __restrict__ dbc, const float* __restrict__ A_log,
            const float* __restrict__ Dp, const float* __restrict__ h0,
            float* __restrict__ y)
{
    __shared__ float Bsh[CHUNK][NST];
    __shared__ float Csh[CHUNK][NST];
    const int d = blockIdx.x * 256 + threadIdx.x;
    const int c = blockIdx.y;
    for (int i = threadIdx.x; i < CHUNK * NST; i += 256) {
        int t = i >> 4;
        int n = i & 15;
        Bsh[t][n] = dbc[(size_t)(c*CHUNK + t) * 96 + 64 + n];
        Csh[t][n] = dbc[(size_t)(c*CHUNK + t) * 96 + 80 + n];
    }
    __syncthreads();

    float a[NST];
    bool fast;
    float a0;
    load_A_fast(A_log, d, a, fast, a0);
    float Dv = Dp[d];

    float h[NST];
    #pragma unroll
    for (int n = 0; n < NST; n++) h[n] = h0[((size_t)c * NST + n) * DI + d];

    const int t0 = c * CHUNK;
    for (int t = 0; t < CHUNK; t++) {
        float dlt = delta[(size_t)(t0 + t) * DI + d];
        float uu  = u[(size_t)(t0 + t) * DI + d];
        float du  = dlt * uu;
        float dAv[NST];
        if (fast) {
            float e = __expf(dlt * a0);
            float w = e;
            #pragma unroll
            for (int n = 0; n < NST; n++) { dAv[n] = w; w *= e; }
        } else {
            #pragma unroll
            for (int n = 0; n < NST; n++) dAv[n] = __expf(dlt * a[n]);
        }
        float yv = 0.f;
        #pragma unroll
        for (int n = 0; n < NST; n++) {
            h[n] = fmaf(dAv[n], h[n], du * Bsh[t][n]);
            yv = fmaf(h[n], Csh[t][n], yv);
        }
        y[(size_t)(t0 + t) * DI + d] = fmaf(Dv, uu, yv);
    }
}

// ---------------- host ------------------------------------------------------
extern "C" void kernel_launch(void* const* d_in, const int* in_sizes, int n_in,
                              void* d_out, int out_size)
{
    const float* x         = (const float*)d_in[0];
    const float* pos_enc   = (const float*)d_in[1];
    const float* ln_g      = (const float*)d_in[2];
    const float* ln_b      = (const float*)d_in[3];
    const float* innorm_g  = (const float*)d_in[4];
    const float* innorm_b  = (const float*)d_in[5];
    const float* in_proj_w = (const float*)d_in[6];
    const float* in_proj_b = (const float*)d_in[7];
    const float* conv_w    = (const float*)d_in[8];
    const float* conv_b    = (const float*)d_in[9];
    const float* deltaBC_w = (const float*)d_in[10];
    const float* dt_proj_w = (const float*)d_in[11];
    const float* dt_proj_b = (const float*)d_in[12];
    const float* A_log     = (const float*)d_in[13];
    const float* Dp        = (const float*)d_in[14];
    const float* outnorm_g = (const float*)d_in[15];
    const float* outnorm_b = (const float*)d_in[16];
    const float* out_proj_w= (const float*)d_in[17];
    const float* out_proj_b= (const float*)d_in[18];

    float* enc = 0;
    float* xz = 0;
    float* u = 0;
    float* dbc = 0;
    float* dbcp = 0;
    float* delta = 0;
    float* y = 0;
    float* hl = 0;
    float* pp = 0;
    float* h0 = 0;
    __nv_bfloat16* hbufs = 0;
    __nv_bfloat16* usplit = 0;
    __nv_bfloat16* dbcs = 0;
    __nv_bfloat16* y2s = 0;
    __nv_bfloat16* win = 0;
    __nv_bfloat16* wdbc = 0;
    __nv_bfloat16* wdt = 0;
    __nv_bfloat16* wout = 0;
    cudaGetSymbolAddress((void**)&enc,   g_enc);
    cudaGetSymbolAddress((void**)&xz,    g_xz);
    cudaGetSymbolAddress((void**)&u,     g_u);
    cudaGetSymbolAddress((void**)&dbc,   g_dbc);
    cudaGetSymbolAddress((void**)&dbcp,  g_dbcp);
    cudaGetSymbolAddress((void**)&delta, g_delta);
    cudaGetSymbolAddress((void**)&y,     g_y);
    cudaGetSymbolAddress((void**)&hl,    g_hl);
    cudaGetSymbolAddress((void**)&pp,    g_pp);
    cudaGetSymbolAddress((void**)&h0,    g_h0);
    cudaGetSymbolAddress((void**)&hbufs, g_hbufs);
    cudaGetSymbolAddress((void**)&usplit,g_us);
    cudaGetSymbolAddress((void**)&dbcs,  g_dbcs);
    cudaGetSymbolAddress((void**)&y2s,   g_y2s);
    cudaGetSymbolAddress((void**)&win,   g_win);
    cudaGetSymbolAddress((void**)&wdbc,  g_wdbc);
    cudaGetSymbolAddress((void**)&wdt,   g_wdt);
    cudaGetSymbolAddress((void**)&wout,  g_wout);

    // weight splits (recomputed every call — determinism)
    {
        int n1 = NL * 2*DI * DM;
        wsplit<<<(n1+255)/256, 256>>>(in_proj_w, win, NL*2*DI, DM);
        int n2 = NL * DM * DI;
        wsplit<<<(n2+255)/256, 256>>>(out_proj_w, wout, NL*DM, DI);
        int n3 = NL * DI * 64;
        wsplit<<<(n3+255)/256, 256>>>(dt_proj_w, wdt, NL*DI, 64);
        for (int l = 0; l < NL; l++) {
            int n4 = 96 * DI;
            wsplit<<<(n4+255)/256, 256>>>(deltaBC_w + (size_t)l*96*DI,
                                          wdbc + (size_t)l*128*3*DI, 96, DI);
        }
    }

    // pre-encoder: enc = LN(x + pos_enc), eps=1e-6
    ln_kernel<4,1,0><<<SEQ, 256>>>(x, pos_enc, DM, 0, ln_g, ln_b, enc, (__nv_bfloat16*)0, DM, 1e-6f);

    for (int l = 0; l < NL; l++) {
        // 1) hbufs = split(LN(enc))
        ln_kernel<4,0,DM><<<SEQ, 256>>>(enc, (const float*)0, 0, 0,
                                        innorm_g + (size_t)l*DM, innorm_b + (size_t)l*DM,
                                        (float*)0, hbufs, DM, 1e-5f);
        // 2) xz = hbuf @ in_proj_w^T + b  (M=4096 N=4096 K'=3072)
        gemm_mma<1><<<dim3(2*DI/128, SEQ/128, 1), 128>>>(
            hbufs, 3*DM, win + (size_t)l*2*DI*3*DM, 3*DM,
            in_proj_b + (size_t)l*2*DI, xz, 2*DI, 3*DM, 2*DI, 0LL);
        // 3) depthwise conv -> u (+split)
        conv_kernel<<<SEQ*DI/256, 256>>>(xz, conv_w + (size_t)l*DI*3,
                                         conv_b + (size_t)l*DI, u, usplit);
        // 4) dbc = u @ deltaBC_w^T (N=96 pad 128, K'=6144, split-K=4)
        gemm_mma<0><<<dim3(1, SEQ/128, KSP), 128>>>(
            usplit, 3*DI, wdbc + (size_t)l*128*3*DI, 3*DI,
            (const float*)0, dbcp, 96, (3*DI)/KSP, 96, (long long)SEQ*96);
        reduce_ks<<<(SEQ*96 + 255)/256, 256>>>(dbcp, dbc, SEQ*96);
        split_dbc<<<SEQ*64/256, 256>>>(dbc, dbcs);
        // 5) delta = softplus(dbc[:,:64] @ dt_proj_w^T + b)  (K'=192)
        gemm_mma<2><<<dim3(DI/128, SEQ/128, 1), 128>>>(
            dbcs, 192, wdt + (size_t)l*DI*192, 192,
            dt_proj_b + (size_t)l*DI, delta, DI, 192, DI, 0LL);
        // 6) chunked selective scan
        scan_pass_a<<<dim3(DI/256, NCH), 256>>>(delta, u, dbc,
                                                A_log + (size_t)l*DI*NST, hl, pp);
        scan_pass_b<<<(NST*DI)/256, 256>>>(hl, pp, h0);
        scan_pass_c<<<dim3(DI/256, NCH), 256>>>(delta, u, dbc,
                                                A_log + (size_t)l*DI*NST,
                                                Dp + (size_t)l*DI, h0, y);
        // 7) y2s = split(LN(y) * silu(z))
        ln_kernel<8,2,DI><<<SEQ, 256>>>(y, xz, 2*DI, DI,
                                        outnorm_g + (size_t)l*DI, outnorm_b + (size_t)l*DI,
                                        (float*)0, y2s, DI, 1e-5f);
        // 8) enc = y2 @ out_proj_w^T + b + enc  (K'=6144)
        gemm_mma<3><<<dim3(DM/128, SEQ/128, 1), 128>>>(
            y2s, 3*DI, wout + (size_t)l*DM*3*DI, 3*DI,
            out_proj_b + (size_t)l*DM, enc, DM, 3*DI, DM, 0LL);
    }

    cudaMemcpyAsync(d_out, enc, sizeof(float) * (size_t)out_size,
                    cudaMemcpyDeviceToDevice);
}

// round 14
// speedup vs baseline: 2.2639x; 1.2166x over previous
#include <cuda_runtime.h>
#include <cuda_bf16.h>
#include <cuda_fp16.h>
#include <cstdint>
#include <math.h>

#define SEQ   4096
#define DM    1024
#define DI    2048
#define NST   16
#define NL    4
#define NCH   64
#define CHUNK 64
#define KSP   4          // split-K factor for deltaBC GEMM

// ---------------- scratch (device globals; no allocation allowed) ----------
__device__ float g_enc[SEQ*DM];
__device__ float g_xz[SEQ*2*DI];
__device__ float g_u[SEQ*DI];
__device__ float g_dbc[SEQ*96];
__device__ float g_dbcp[KSP*SEQ*96];
__device__ float g_delta[SEQ*DI];
__device__ float g_y[SEQ*DI];
__device__ float g_hl[NCH*NST*DI];
__device__ float g_pp[NCH*NST*DI];
__device__ float g_h0[NCH*NST*DI];
// bf16 3-term split activations (A' = [hi | lo | hi])  — delta-sensitive path
__device__ __nv_bfloat16 g_us[SEQ*3*DI];
__device__ __nv_bfloat16 g_dbcs[SEQ*3*64];
// fp16 2-term split activations (A' = [hi | lo]) — big GEMMs
__device__ __half g_hbufs_h[SEQ*2*DM];
__device__ __half g_y2s_h[SEQ*2*DI];
// weights: bf16 3-term (B' = [hi | hi | lo]) for dbc/dt
__device__ __nv_bfloat16 g_wdbc[NL*128*(3*DI)];   // padded 96->128 rows
__device__ __nv_bfloat16 g_wdt[NL*DI*(3*64)];
// weights: fp16 2-term (B' = [hi | hi]) for in/out proj
__device__ __half g_win_h[NL*(2*DI)*(2*DM)];
__device__ __half g_wout_h[NL*DM*(2*DI)];

// ======================= helpers ============================================
__device__ __forceinline__ unsigned int smem_u32(const void* smem_ptr) {
    unsigned int addr;
    asm("{ .reg .u64 tmp; cvta.to.shared.u64 tmp, %1; cvt.u32.u64 %0, tmp; }"
        : "=r"(addr) : "l"(smem_ptr));
    return addr;
}

#define LDSM_X4(r0, r1, r2, r3, addr) \
    asm volatile( \
        "ldmatrix.sync.aligned.m8n8.x4.shared.b16 {%0, %1, %2, %3}, [%4];" \
        : "=r"(r0), "=r"(r1), "=r"(r2), "=r"(r3) : "r"(addr))

#define MMA16816_BF(c, a, b) \
    asm volatile( \
        "mma.sync.aligned.m16n8k16.row.col.f32.bf16.bf16.f32 " \
        "{%0, %1, %2, %3}, {%4, %5, %6, %7}, {%8, %9}, {%0, %1, %2, %3};" \
        : "+f"((c)[0]), "+f"((c)[1]), "+f"((c)[2]), "+f"((c)[3]) \
        : "r"((a)[0]), "r"((a)[1]), "r"((a)[2]), "r"((a)[3]), \
          "r"((b)[0]), "r"((b)[1]))

#define MMA16816_HF(c, a, b) \
    asm volatile( \
        "mma.sync.aligned.m16n8k16.row.col.f32.f16.f16.f32 " \
        "{%0, %1, %2, %3}, {%4, %5, %6, %7}, {%8, %9}, {%0, %1, %2, %3};" \
        : "+f"((c)[0]), "+f"((c)[1]), "+f"((c)[2]), "+f"((c)[3]) \
        : "r"((a)[0]), "r"((a)[1]), "r"((a)[2]), "r"((a)[3]), \
          "r"((b)[0]), "r"((b)[1]))

#define CP_ASYNC16(dst, src) \
    asm volatile("cp.async.cg.shared.global [%0], [%1], 16;" \
                 :: "r"(dst), "l"(src) : "memory")
#define CP_COMMIT() \
    asm volatile("cp.async.commit_group;" ::: "memory")
#define CP_WAIT1() \
    asm volatile("cp.async.wait_group 1;" ::: "memory")

// ======================= 16-bit mma.sync GEMM (NT), cp.async pipelined ======
// C[m,n] = sum_k A'[m,k] * B'[n,k].  A',B' are 16-bit (bf16 if F16=0, fp16
// if F16=1; pointers passed as bf16* regardless — bits interpreted by MMA).
// Kspan % 32 == 0. 128x128 CTA tile, 128 threads (4 warps = 2m x 2n, warp
// tile 64x64). K chunks of 32; 3 smem stages (16KB each, 48KB static).
// smem rows 64B; swizzle: 16B-unit col ^= (row & 3).
// blockIdx.z (split-K): k offset = z*Kspan, C += z*sliceStride.
// EPI: 0 store (masked to Nact), 1 +bias, 2 +bias->softplus, 3 +bias +C
template<int EPI, int F16>
__global__ void __launch_bounds__(128)
gemm_mma(const __nv_bfloat16* __restrict__ A, int lda,
         const __nv_bfloat16* __restrict__ B, int ldb,
         const float* __restrict__ bias,
         float* __restrict__ C, int ldc, int Kspan, int Nact,
         long long sliceStride)
{
    __shared__ __align__(128) unsigned char smem_raw[3 * 16384];

    const int tid  = threadIdx.x;
    const int wid  = tid >> 5;
    const int lane = tid & 31;
    const int wm   = wid >> 1;        // 0..1
    const int wn   = wid & 1;         // 0..1
    const int rowBase = blockIdx.y * 128;
    const int colBase = blockIdx.x * 128;
    const int kOff = blockIdx.z * Kspan;
    const int nch = Kspan >> 5;       // K chunks of 32
    C += (long long)blockIdx.z * sliceStride;

    const unsigned int sbase = smem_u32(smem_raw);

    float acc[4][8][4];
    #pragma unroll
    for (int mf = 0; mf < 4; mf++)
        #pragma unroll
        for (int nf = 0; nf < 8; nf++)
            #pragma unroll
            for (int r = 0; r < 4; r++) acc[mf][nf][r] = 0.f;

    // ldmatrix per-lane row/col-16B selectors
    const int aRow = (lane & 7) + ((lane >> 3) & 1) * 8;
    const int aC16 = (lane >> 4);            // 0/1 -> k 0..7 / 8..15
    const int bRow = (lane & 7) + ((lane >> 4) & 1) * 8;
    const int bC16 = ((lane >> 3) & 1);

    const __nv_bfloat16* Atile = A + (size_t)rowBase * lda + kOff;
    const __nv_bfloat16* Btile = B + (size_t)colBase * ldb + kOff;

    // loader: 1024 16B units per chunk (A 0..511, B 512..1023); 8 per thread
    unsigned int so[8];
    const __nv_bfloat16* gp[8];
    #pragma unroll
    for (int j = 0; j < 8; j++) {
        int unit = tid + j * 128;                 // 0..1023
        int isB = (unit >= 512);
        int u = unit & 511;
        int r = u >> 2;
        int cc = u & 3;
        so[j] = (unsigned int)(isB * 8192 + r * 64 + ((cc ^ (r & 3)) << 4));
        const __nv_bfloat16* base = isB ? Btile : Atile;
        int ld = isB ? ldb : lda;
        gp[j] = base + (size_t)r * ld + cc * 8;
    }

    // prologue: stages 0,1
    {
        #pragma unroll
        for (int j = 0; j < 8; j++) CP_ASYNC16(sbase + so[j], gp[j]);
        CP_COMMIT();
        if (nch > 1) {
            #pragma unroll
            for (int j = 0; j < 8; j++)
                CP_ASYNC16(sbase + 16384u + so[j], gp[j] + 32);
        }
        CP_COMMIT();
    }

    int stage = 0;
    for (int c = 0; c < nch; c++) {
        CP_WAIT1();
        __syncthreads();

        // issue load for chunk c+2 into the stage freed at iteration c-1
        if (c + 2 < nch) {
            int s2 = stage + 2; if (s2 >= 3) s2 -= 3;
            unsigned int st = sbase + (unsigned int)s2 * 16384u;
            int co = (c + 2) * 32;
            #pragma unroll
            for (int j = 0; j < 8; j++) CP_ASYNC16(st + so[j], gp[j] + co);
        }
        CP_COMMIT();

        const unsigned int sA = sbase + (unsigned int)stage * 16384u;
        const unsigned int sB = sA + 8192u;

        #pragma unroll
        for (int ks = 0; ks < 2; ks++) {
            unsigned int afr[4][4];
            unsigned int bfr[8][2];
            #pragma unroll
            for (int mf = 0; mf < 4; mf++) {
                int r = wm * 64 + mf * 16 + aRow;
                int c16 = ks * 2 + aC16;
                unsigned int off = (unsigned int)(r * 64 + ((c16 ^ (r & 3)) << 4));
                LDSM_X4(afr[mf][0], afr[mf][1], afr[mf][2], afr[mf][3], sA + off);
            }
            #pragma unroll
            for (int bp = 0; bp < 4; bp++) {
                int r = wn * 64 + bp * 16 + bRow;
                int c16 = ks * 2 + bC16;
                unsigned int off = (unsigned int)(r * 64 + ((c16 ^ (r & 3)) << 4));
                LDSM_X4(bfr[bp*2][0], bfr[bp*2][1],
                        bfr[bp*2+1][0], bfr[bp*2+1][1], sB + off);
            }
            #pragma unroll
            for (int mf = 0; mf < 4; mf++)
                #pragma unroll
                for (int nf = 0; nf < 8; nf++) {
                    if (F16) { MMA16816_HF(acc[mf][nf], afr[mf], bfr[nf]); }
                    else     { MMA16816_BF(acc[mf][nf], afr[mf], bfr[nf]); }
                }
        }

        stage++; if (stage >= 3) stage -= 3;
    }

    // ---- epilogue ----
    #pragma unroll
    for (int mf = 0; mf < 4; mf++) {
        int r0 = rowBase + wm * 64 + mf * 16 + (lane >> 2);
        #pragma unroll
        for (int nf = 0; nf < 8; nf++) {
            int c0 = colBase + wn * 64 + nf * 8 + (lane & 3) * 2;
            if (c0 < Nact) {
                float v0 = acc[mf][nf][0];
                float v1 = acc[mf][nf][1];
                float v2 = acc[mf][nf][2];
                float v3 = acc[mf][nf][3];
                if (EPI >= 1) {
                    float b0 = bias[c0];
                    float b1 = bias[c0 + 1];
                    v0 += b0; v1 += b1; v2 += b0; v3 += b1;
                }
                if (EPI == 2) {
                    v0 = fmaxf(v0, 0.f) + log1pf(expf(-fabsf(v0)));
                    v1 = fmaxf(v1, 0.f) + log1pf(expf(-fabsf(v1)));
                    v2 = fmaxf(v2, 0.f) + log1pf(expf(-fabsf(v2)));
                    v3 = fmaxf(v3, 0.f) + log1pf(expf(-fabsf(v3)));
                }
                size_t o0 = (size_t)r0 * ldc + c0;
                size_t o1 = (size_t)(r0 + 8) * ldc + c0;
                if (EPI == 3) {
                    v0 += C[o0]; v1 += C[o0 + 1];
                    v2 += C[o1]; v3 += C[o1 + 1];
                }
                C[o0] = v0; C[o0 + 1] = v1;
                C[o1] = v2; C[o1 + 1] = v3;
            }
        }
    }
}

// ======================= split conversion =================================
__device__ __forceinline__ void split2(float v, __nv_bfloat16& hi, __nv_bfloat16& lo) {
    hi = __float2bfloat16(v);
    lo = __float2bfloat16(v - __bfloat162float(hi));
}
__device__ __forceinline__ void split2h(float v, __half& hi, __half& lo) {
    hi = __float2half_rn(v);
    lo = __float2half_rn(v - __half2float(hi));
}

// bf16 weights: B' = [hi | hi | lo]
__global__ void __launch_bounds__(256)
wsplit(const float* __restrict__ W, __nv_bfloat16* __restrict__ out, int N, int K)
{
    int i = blockIdx.x * 256 + threadIdx.x;
    if (i >= N * K) return;
    int n = i / K;
    int k = i - n * K;
    __nv_bfloat16 hi, lo;
    split2(W[i], hi, lo);
    size_t b = (size_t)n * 3 * K;
    out[b + k] = hi;
    out[b + K + k] = hi;
    out[b + 2 * K + k] = lo;
}

// fp16 weights: B' = [hi | hi]
__global__ void __launch_bounds__(256)
wsplit_h(const float* __restrict__ W, __half* __restrict__ out, int N, int K)
{
    int i = blockIdx.x * 256 + threadIdx.x;
    if (i >= N * K) return;
    int n = i / K;
    int k = i - n * K;
    __half hi = __float2half_rn(W[i]);
    size_t b = (size_t)n * 2 * K;
    out[b + k] = hi;
    out[b + K + k] = hi;
}

// split-K reduce fused with dbc col[0,64) bf16 3-term split
__global__ void __launch_bounds__(256)
reduce_split(const float* __restrict__ part, float* __restrict__ dbc,
             __nv_bfloat16* __restrict__ dbcs)
{
    int i = blockIdx.x * 256 + threadIdx.x;
    if (i >= SEQ * 96) return;
    float s = 0.f;
    #pragma unroll
    for (int z = 0; z < KSP; z++) s += part[(size_t)z * (SEQ * 96) + i];
    dbc[i] = s;
    int row = i / 96;
    int col = i - row * 96;
    if (col < 64) {
        __nv_bfloat16 hi, lo;
        split2(s, hi, lo);
        size_t b = (size_t)row * 192;
        dbcs[b + col] = hi;
        dbcs[b + 64 + col] = lo;
        dbcs[b + 128 + col] = hi;
    }
}

// ---------------- block reduce (sum, sumsq) --------------------------------
__device__ __forceinline__ float2 block_reduce2(float sx, float sq) {
    __shared__ float shx[8];
    __shared__ float shq[8];
    const unsigned m = 0xffffffffu;
    #pragma unroll
    for (int o = 16; o > 0; o >>= 1) {
        sx += __shfl_xor_sync(m, sx, o);
        sq += __shfl_xor_sync(m, sq, o);
    }
    int w = threadIdx.x >> 5;
    if ((threadIdx.x & 31) == 0) { shx[w] = sx; shq[w] = sq; }
    __syncthreads();
    if (threadIdx.x == 0) {
        float ax = 0.f;
        float aq = 0.f;
        #pragma unroll
        for (int i = 0; i < 8; i++) { ax += shx[i]; aq += shq[i]; }
        shx[0] = ax;
        shq[0] = aq;
    }
    __syncthreads();
    return make_float2(shx[0], shq[0]);
}

// ---------------- layernorm family -----------------------------------------
// MODE 0: LN(x); MODE 1: LN(x+x2); MODE 2: LN(x)*silu(x2[row*ld2+off2+i])
// SK==0: write fp32 to outf; SK>0: write fp16 2-term [hi|lo] to outs_h
template<int VPT, int MODE, int SK>
__global__ void __launch_bounds__(256)
ln_kernel(const float* __restrict__ x, const float* __restrict__ x2,
          int ld2, int off2,
          const float* __restrict__ g, const float* __restrict__ b,
          float* __restrict__ outf, __half* __restrict__ outs_h,
          int D, float eps)
{
    const int row = blockIdx.x;
    float v[VPT];
    float sx = 0.f;
    float sq = 0.f;
    #pragma unroll
    for (int i = 0; i < VPT; i++) {
        int idx = threadIdx.x + i * 256;
        float t = x[(size_t)row * D + idx];
        if (MODE == 1) t += x2[(size_t)row * D + idx];
        v[i] = t;
        sx += t;
        sq += t * t;
    }
    float2 s = block_reduce2(sx, sq);
    float mu = s.x / (float)D;
    float var = s.y / (float)D - mu * mu;
    float rs = rsqrtf(var + eps);
    #pragma unroll
    for (int i = 0; i < VPT; i++) {
        int idx = threadIdx.x + i * 256;
        float o = (v[i] - mu) * rs * g[idx] + b[idx];
        if (MODE == 2) {
            float z = x2[(size_t)row * ld2 + off2 + idx];
            o *= z / (1.f + __expf(-z));
        }
        if (SK == 0) {
            outf[(size_t)row * D + idx] = o;
        } else {
            __half hi, lo;
            split2h(o, hi, lo);
            size_t rb = (size_t)row * 2 * SK;
            outs_h[rb + idx] = hi;
            outs_h[rb + SK + idx] = lo;
        }
    }
}

// ---------------- depthwise conv1d k=3, pad=1 (+ bf16 3-term split of u) ----
__global__ void __launch_bounds__(256)
conv_kernel(const float* __restrict__ xz, const float* __restrict__ w,
            const float* __restrict__ b, float* __restrict__ u,
            __nv_bfloat16* __restrict__ usplit)
{
    int idx = blockIdx.x * 256 + threadIdx.x;     // < SEQ*DI
    int d = idx & (DI - 1);
    int t = idx >> 11;
    float w0 = w[d*3+0];
    float w1 = w[d*3+1];
    float w2 = w[d*3+2];
    const float* col = xz + d;
    float xm = (t > 0)       ? col[(size_t)(t-1) * (2*DI)] : 0.f;
    float x0 =                 col[(size_t)t     * (2*DI)];
    float xp = (t < SEQ - 1) ? col[(size_t)(t+1) * (2*DI)] : 0.f;
    float v = fmaf(w0, xm, fmaf(w1, x0, fmaf(w2, xp, b[d])));
    u[idx] = v;
    __nv_bfloat16 hi, lo;
    split2(v, hi, lo);
    size_t rb = (size_t)t * 3 * DI;
    usplit[rb + d] = hi;
    usplit[rb + DI + d] = lo;
    usplit[rb + 2 * DI + d] = hi;
}

// ---------------- scan helpers ---------------------------------------------
__device__ __forceinline__ void load_A_fast(const float* __restrict__ A_log, int d,
                                            float* a, bool& fast, float& a0)
{
    #pragma unroll
    for (int n = 0; n < NST; n++) a[n] = -__expf(A_log[(size_t)d * NST + n]);
    a0 = a[0];
    fast = true;
    #pragma unroll
    for (int n = 1; n < NST; n++)
        fast = fast && (fabsf(a[n] - (float)(n+1) * a0) <= 2e-5f * (float)(n+1));
}

__global__ void __launch_bounds__(256)
scan_pass_a(const float* __restrict__ delta, const float* __restrict__ u,
            const float* __restrict__ dbc, const float* __restrict__ A_log,
            float* __restrict__ hl, float* __restrict__ pp)
{
    __shared__ float Bsh[CHUNK][NST];
    const int d = blockIdx.x * 256 + threadIdx.x;
    const int c = blockIdx.y;
    for (int i = threadIdx.x; i < CHUNK * NST; i += 256) {
        int t = i >> 4;
        int n = i & 15;
        Bsh[t][n] = dbc[(size_t)(c*CHUNK + t) * 96 + 64 + n];
    }
    __syncthreads();

    float a[NST];
    bool fast;
    float a0;
    load_A_fast(A_log, d, a, fast, a0);

    float h[NST];
    float p[NST];
    #pragma unroll
    for (int n = 0; n < NST; n++) { h[n] = 0.f; p[n] = 1.f; }

    const int t0 = c * CHUNK;
    for (int t = 0; t < CHUNK; t++) {
        float dlt = delta[(size_t)(t0 + t) * DI + d];
        float uu  = u[(size_t)(t0 + t) * DI + d];
        float du  = dlt * uu;
        float dAv[NST];
        if (fast) {
            float e = __expf(dlt * a0);
            float w = e;
            #pragma unroll
            for (int n = 0; n < NST; n++) { dAv[n] = w; w *= e; }
        } else {
            #pragma unroll
            for (int n = 0; n < NST; n++) dAv[n] = __expf(dlt * a[n]);
        }
        #pragma unroll
        for (int n = 0; n < NST; n++) {
            h[n] = fmaf(dAv[n], h[n], du * Bsh[t][n]);
            p[n] *= dAv[n];
        }
    }
    #pragma unroll
    for (int n = 0; n < NST; n++) {
        size_t o = ((size_t)c * NST + n) * DI + d;
        hl[o] = h[n];
        pp[o] = p[n];
    }
}

__global__ void __launch_bounds__(256)
scan_pass_b(const float* __restrict__ hl, const float* __restrict__ pp,
            float* __restrict__ h0)
{
    int i = blockIdx.x * 256 + threadIdx.x;
    if (i >= NST * DI) return;
    float h = 0.f;
    for (int c = 0; c < NCH; c++) {
        size_t idx = (size_t)c * NST * DI + i;
        h0[idx] = h;
        h = fmaf(pp[idx], h, hl[idx]);
    }
}

__global__ void __launch_bounds__(256)
scan_pass_c(const float* __restrict__ delta, const float* __restrict__ u,
            const float* __restrict__ dbc, const float* __restrict__ A_log,
            const float* __restrict__ Dp, const float* __restrict__ h0,
            float* __restrict__ y)
{
    __shared__ float Bsh[CHUNK][NST];
    __shared__ float Csh[CHUNK][NST];
    const int d = blockIdx.x * 256 + threadIdx.x;
    const int c = blockIdx.y;
    for (int i = threadIdx.x; i < CHUNK * NST; i += 256) {
        int t = i >> 4;
        int n = i & 15;
        Bsh[t][n] = dbc[(size_t)(c*CHUNK + t) * 96 + 64 + n];
        Csh[t][n] = dbc[(size_t)(c*CHUNK + t) * 96 + 80 + n];
    }
    __syncthreads();

    float a[NST];
    bool fast;
    float a0;
    load_A_fast(A_log, d, a, fast, a0);
    float Dv = Dp[d];

    float h[NST];
    #pragma unroll
    for (int n = 0; n < NST; n++) h[n] = h0[((size_t)c * NST + n) * DI + d];

    const int t0 = c * CHUNK;
    for (int t = 0; t < CHUNK; t++) {
        float dlt = delta[(size_t)(t0 + t) * DI + d];
        float uu  = u[(size_t)(t0 + t) * DI + d];
        float du  = dlt * uu;
        float dAv[NST];
        if (fast) {
            float e = __expf(dlt * a0);
            float w = e;
            #pragma unroll
            for (int n = 0; n < NST; n++) { dAv[n] = w; w *= e; }
        } else {
            #pragma unroll
            for (int n = 0; n < NST; n++) dAv[n] = __expf(dlt * a[n]);
        }
        float yv = 0.f;
        #pragma unroll
        for (int n = 0; n < NST; n++) {
            h[n] = fmaf(dAv[n], h[n], du * Bsh[t][n]);
            yv = fmaf(h[n], Csh[t][n], yv);
        }
        y[(size_t)(t0 + t) * DI + d] = fmaf(Dv, uu, yv);
    }
}

// ---------------- host ------------------------------------------------------
extern "C" void kernel_launch(void* const* d_in, const int* in_sizes, int n_in,
                              void* d_out, int out_size)
{
    const float* x         = (const float*)d_in[0];
    const float* pos_enc   = (const float*)d_in[1];
    const float* ln_g      = (const float*)d_in[2];
    const float* ln_b      = (const float*)d_in[3];
    const float* innorm_g  = (const float*)d_in[4];
    const float* innorm_b  = (const float*)d_in[5];
    const float* in_proj_w = (const float*)d_in[6];
    const float* in_proj_b = (const float*)d_in[7];
    const float* conv_w    = (const float*)d_in[8];
    const float* conv_b    = (const float*)d_in[9];
    const float* deltaBC_w = (const float*)d_in[10];
    const float* dt_proj_w = (const float*)d_in[11];
    const float* dt_proj_b = (const float*)d_in[12];
    const float* A_log     = (const float*)d_in[13];
    const float* Dp        = (const float*)d_in[14];
    const float* outnorm_g = (const float*)d_in[15];
    const float* outnorm_b = (const float*)d_in[16];
    const float* out_proj_w= (const float*)d_in[17];
    const float* out_proj_b= (const float*)d_in[18];

    float* enc = 0;
    float* xz = 0;
    float* u = 0;
    float* dbc = 0;
    float* dbcp = 0;
    float* delta = 0;
    float* y = 0;
    float* hl = 0;
    float* pp = 0;
    float* h0 = 0;
    __nv_bfloat16* usplit = 0;
    __nv_bfloat16* dbcs = 0;
    __nv_bfloat16* wdbc = 0;
    __nv_bfloat16* wdt = 0;
    __half* hbufs_h = 0;
    __half* y2s_h = 0;
    __half* win_h = 0;
    __half* wout_h = 0;
    cudaGetSymbolAddress((void**)&enc,     g_enc);
    cudaGetSymbolAddress((void**)&xz,      g_xz);
    cudaGetSymbolAddress((void**)&u,       g_u);
    cudaGetSymbolAddress((void**)&dbc,     g_dbc);
    cudaGetSymbolAddress((void**)&dbcp,    g_dbcp);
    cudaGetSymbolAddress((void**)&delta,   g_delta);
    cudaGetSymbolAddress((void**)&y,       g_y);
    cudaGetSymbolAddress((void**)&hl,      g_hl);
    cudaGetSymbolAddress((void**)&pp,      g_pp);
    cudaGetSymbolAddress((void**)&h0,      g_h0);
    cudaGetSymbolAddress((void**)&usplit,  g_us);
    cudaGetSymbolAddress((void**)&dbcs,    g_dbcs);
    cudaGetSymbolAddress((void**)&wdbc,    g_wdbc);
    cudaGetSymbolAddress((void**)&wdt,     g_wdt);
    cudaGetSymbolAddress((void**)&hbufs_h, g_hbufs_h);
    cudaGetSymbolAddress((void**)&y2s_h,   g_y2s_h);
    cudaGetSymbolAddress((void**)&win_h,   g_win_h);
    cudaGetSymbolAddress((void**)&wout_h,  g_wout_h);

    // weight splits (recomputed every call — determinism)
    {
        int n1 = NL * 2*DI * DM;
        wsplit_h<<<(n1+255)/256, 256>>>(in_proj_w, win_h, NL*2*DI, DM);
        int n2 = NL * DM * DI;
        wsplit_h<<<(n2+255)/256, 256>>>(out_proj_w, wout_h, NL*DM, DI);
        int n3 = NL * DI * 64;
        wsplit<<<(n3+255)/256, 256>>>(dt_proj_w, wdt, NL*DI, 64);
        for (int l = 0; l < NL; l++) {
            int n4 = 96 * DI;
            wsplit<<<(n4+255)/256, 256>>>(deltaBC_w + (size_t)l*96*DI,
                                          wdbc + (size_t)l*128*3*DI, 96, DI);
        }
    }

    // pre-encoder: enc = LN(x + pos_enc), eps=1e-6
    ln_kernel<4,1,0><<<SEQ, 256>>>(x, pos_enc, DM, 0, ln_g, ln_b, enc, (__half*)0, DM, 1e-6f);

    for (int l = 0; l < NL; l++) {
        // 1) hbufs = fp16 2-term split(LN(enc))
        ln_kernel<4,0,DM><<<SEQ, 256>>>(enc, (const float*)0, 0, 0,
                                        innorm_g + (size_t)l*DM, innorm_b + (size_t)l*DM,
                                        (float*)0, hbufs_h, DM, 1e-5f);
        // 2) xz = hbuf @ in_proj_w^T + b  (fp16, M=4096 N=4096 K'=2048)
        gemm_mma<1,1><<<dim3(2*DI/128, SEQ/128, 1), 128>>>(
            (const __nv_bfloat16*)hbufs_h, 2*DM,
            (const __nv_bfloat16*)(win_h + (size_t)l*2*DI*2*DM), 2*DM,
            in_proj_b + (size_t)l*2*DI, xz, 2*DI, 2*DM, 2*DI, 0LL);
        // 3) depthwise conv -> u (+bf16 3-term split)
        conv_kernel<<<SEQ*DI/256, 256>>>(xz, conv_w + (size_t)l*DI*3,
                                         conv_b + (size_t)l*DI, u, usplit);
        // 4) dbc = u @ deltaBC_w^T (bf16 3-term, N pad 128, K'=6144, split-K)
        gemm_mma<0,0><<<dim3(1, SEQ/128, KSP), 128>>>(
            usplit, 3*DI, wdbc + (size_t)l*128*3*DI, 3*DI,
            (const float*)0, dbcp, 96, (3*DI)/KSP, 96, (long long)SEQ*96);
        reduce_split<<<(SEQ*96 + 255)/256, 256>>>(dbcp, dbc, dbcs);
        // 5) delta = softplus(dbc[:,:64] @ dt_proj_w^T + b)  (bf16, K'=192)
        gemm_mma<2,0><<<dim3(DI/128, SEQ/128, 1), 128>>>(
            dbcs, 192, wdt + (size_t)l*DI*192, 192,
            dt_proj_b + (size_t)l*DI, delta, DI, 192, DI, 0LL);
        // 6) chunked selective scan
        scan_pass_a<<<dim3(DI/256, NCH), 256>>>(delta, u, dbc,
                                                A_log + (size_t)l*DI*NST, hl, pp);
        scan_pass_b<<<(NST*DI)/256, 256>>>(hl, pp, h0);
        scan_pass_c<<<dim3(DI/256, NCH), 256>>>(delta, u, dbc,
                                                A_log + (size_t)l*DI*NST,
                                                Dp + (size_t)l*DI, h0, y);
        // 7) y2s = fp16 2-term split(LN(y) * silu(z))
        ln_kernel<8,2,DI><<<SEQ, 256>>>(y, xz, 2*DI, DI,
                                        outnorm_g + (size_t)l*DI, outnorm_b + (size_t)l*DI,
                                        (float*)0, y2s_h, DI, 1e-5f);
        // 8) enc = y2 @ out_proj_w^T + b + enc  (fp16, K'=4096)
        gemm_mma<3,1><<<dim3(DM/128, SEQ/128, 1), 128>>>(
            (const __nv_bfloat16*)y2s_h, 2*DI,
            (const __nv_bfloat16*)(wout_h + (size_t)l*DM*2*DI), 2*DI,
            out_proj_b + (size_t)l*DM, enc, DM, 2*DI, DM, 0LL);
    }

    cudaMemcpyAsync(d_out, enc, sizeof(float) * (size_t)out_size,
                    cudaMemcpyDeviceToDevice);
}